// round 13
// baseline (speedup 1.0000x reference)
#include <cuda_runtime.h>
#include <cuda_bf16.h>
#include <math.h>
#include <float.h>
#include <stdint.h>

#define BS_TOK 2048
#define NQn 16
#define NSn 8
#define KDn 64
#define NKn 2048
#define VDn 128
#define MEMn 512
#define LN_EPS 1e-5f
#define NROWS (BS_TOK * NQn)     // 32768 (token,slot) rows

// ---------------------------------------------------------------------------
// Scratch globals
// ---------------------------------------------------------------------------
__device__ __nv_bfloat16 g_xhi[BS_TOK * 512],        g_xlo[BS_TOK * 512];
__device__ __nv_bfloat16 g_wqt_hi[1024 * 512],       g_wqt_lo[1024 * 512];
__device__ __nv_bfloat16 g_qhi[NROWS * KDn],         g_qlo[NROWS * KDn];
__device__ __nv_bfloat16 g_khi[NSn * NKn * KDn],     g_klo[NSn * NKn * KDn];
__device__ __nv_bfloat16 g_wmemt_hi[MEMn * VDn],     g_wmemt_lo[MEMn * VDn];
__device__ __nv_bfloat16 g_wrmt_hi[MEMn * KDn],      g_wrmt_lo[MEMn * KDn];
__device__ float         g_brm[MEMn];
__device__ __nv_bfloat16 g_atthi[NROWS * VDn],       g_attlo[NROWS * VDn];
// attention staging: per row: 4 parts x 8 sub-runs x 8 packed (score,idx)
__device__ int   g_topp[(size_t)NROWS * 256];
__device__ float g_pw  [(size_t)NROWS * 8];
__device__ int   g_pidx[(size_t)NROWS * 8];

// ---------------------------------------------------------------------------
// Helpers
// ---------------------------------------------------------------------------
__device__ __forceinline__ uint32_t smem_u32(const void* p) {
    uint32_t a;
    asm("{ .reg .u64 t; cvta.to.shared.u64 t, %1; cvt.u32.u64 %0, t; }" : "=r"(a) : "l"(p));
    return a;
}
__device__ __forceinline__ uint32_t sw128(uint32_t off) { return off ^ ((off >> 3) & 0x70); }

__device__ __forceinline__ void mma16816(float c[4], const uint32_t a[4], const uint32_t b[2])
{
    asm("mma.sync.aligned.m16n8k16.row.col.f32.bf16.bf16.f32 "
        "{%0,%1,%2,%3},{%4,%5,%6,%7},{%8,%9},{%0,%1,%2,%3};"
        : "+f"(c[0]), "+f"(c[1]), "+f"(c[2]), "+f"(c[3])
        : "r"(a[0]), "r"(a[1]), "r"(a[2]), "r"(a[3]), "r"(b[0]), "r"(b[1]));
}
__device__ __forceinline__ void ldsm4(uint32_t& r0, uint32_t& r1, uint32_t& r2, uint32_t& r3, uint32_t addr)
{
    asm volatile("ldmatrix.sync.aligned.m8n8.x4.shared.b16 {%0,%1,%2,%3}, [%4];"
                 : "=r"(r0), "=r"(r1), "=r"(r2), "=r"(r3) : "r"(addr));
}
__device__ __forceinline__ void split_bf16(float v, __nv_bfloat16& h, __nv_bfloat16& l) {
    h = __float2bfloat16(v);
    l = __float2bfloat16(v - __bfloat162float(h));
}
// |s| <= 8 guaranteed (q LayerNorm'd, gamma=1 -> ||q||=8; keys unit).
// pack = (rint(s*2^15) << 11) | (2047 - idx): signed-monotone in s,
// ties break toward lower idx (reference top_k semantics).
__device__ __forceinline__ int packsc(float s, int idx) {
    const int q = __float2int_rn(s * 32768.f);
    return (q << 11) | (2047 - idx);
}
// branchless top-8 insert (descending) via IMNMX exchange chain
__device__ __forceinline__ void insp(int s, int tv[8]) {
#pragma unroll
    for (int i = 0; i < 8; ++i) {
        const int lo = min(tv[i], s);
        tv[i] = max(tv[i], s);
        s = lo;
    }
}

// ---------------------------------------------------------------------------
// Prep
// ---------------------------------------------------------------------------
__global__ void prep_weights(const float* __restrict__ x, const float* __restrict__ Wq,
                             const float* __restrict__ Wres, const float* __restrict__ Wmem,
                             const float* __restrict__ bres, const float* __restrict__ bmem)
{
    const int b = blockIdx.x;
    const int tid = threadIdx.x;
    __nv_bfloat16 h, l;
    if (b < 4096) {
        const int i = b * 256 + tid;
        split_bf16(x[i], h, l);
        g_xhi[i] = h; g_xlo[i] = l;
    } else if (b < 6144) {
        const int i = (b - 4096) * 256 + tid;
        const int k = i >> 10, n = i & 1023;
        split_bf16(Wq[i], h, l);
        g_wqt_hi[(size_t)n * 512 + k] = h;
        g_wqt_lo[(size_t)n * 512 + k] = l;
    } else if (b < 6400) {
        const int i = (b - 6144) * 256 + tid;
        const int k = i >> 9, n = i & 511;
        split_bf16(Wmem[i], h, l);
        g_wmemt_hi[(size_t)n * 128 + k] = h;
        g_wmemt_lo[(size_t)n * 128 + k] = l;
    } else if (b < 6528) {
        const int i = (b - 6400) * 256 + tid;
        const int m = i >> 9, n = i & 511;
        float acc = 0.f;
#pragma unroll 8
        for (int k = 0; k < VDn; ++k)
            acc += Wres[m * VDn + k] * Wmem[k * MEMn + n];
        split_bf16(acc, h, l);
        g_wrmt_hi[(size_t)n * KDn + m] = h;
        g_wrmt_lo[(size_t)n * KDn + m] = l;
    } else if (b < 6530) {
        const int n = (b - 6528) * 256 + tid;
        float acc = bmem[n];
#pragma unroll 8
        for (int k = 0; k < VDn; ++k)
            acc += bres[k] * Wmem[k * MEMn + n];
        g_brm[n] = acc;
    }
}

__global__ void knorm_split_kernel(const float* __restrict__ keys)
{
    const int warp = (blockIdx.x * blockDim.x + threadIdx.x) >> 5;
    const int lane = threadIdx.x & 31;
    if (warp >= NSn * NKn) return;
    const float* src = keys + (size_t)warp * KDn;
    float v0 = src[lane], v1 = src[lane + 32];
    float sq = v0 * v0 + v1 * v1;
#pragma unroll
    for (int o = 16; o > 0; o >>= 1) sq += __shfl_xor_sync(0xffffffffu, sq, o);
    const float scale = rsqrtf(sq);
    __nv_bfloat16 h, l;
    split_bf16(v0 * scale, h, l); g_khi[(size_t)warp * KDn + lane] = h;      g_klo[(size_t)warp * KDn + lane] = l;
    split_bf16(v1 * scale, h, l); g_khi[(size_t)warp * KDn + lane + 32] = h; g_klo[(size_t)warp * KDn + lane + 32] = l;
}

// ---------------------------------------------------------------------------
// gemm_q: q = LN(x @ Wq^T' + bq), fused LN epilogue -> g_qhi/qlo. 64KB smem.
// ---------------------------------------------------------------------------
#define GSM_AH 0
#define GSM_AL 16384
#define GSM_BH 32768
#define GSM_BL 49152
#define GEMM_SMEM 65536

__global__ __launch_bounds__(256) void gemm_q_kernel(const float* __restrict__ bias,
                                                     const float* __restrict__ gamma,
                                                     const float* __restrict__ beta)
{
    extern __shared__ char smem[];
    const uint32_t sb = smem_u32(smem);
    const int tid  = threadIdx.x;
    const int lane = tid & 31;
    const int w    = tid >> 5;
    const int wm   = w & 3;
    const int wn   = w >> 2;
    const int m0   = blockIdx.y << 7;
    const int n0   = blockIdx.x << 7;
    const int K    = 512;

    float c[2][8][4];
#pragma unroll
    for (int mt = 0; mt < 2; ++mt)
#pragma unroll
        for (int nt = 0; nt < 8; ++nt)
#pragma unroll
            for (int j = 0; j < 4; ++j) c[mt][nt][j] = 0.f;

    const uint32_t a_off0 = (uint32_t)((wm * 32 + (lane & 15)) * 128 + ((lane >> 4) << 4));
    const uint32_t a_off1 = (uint32_t)((wm * 32 + 16 + (lane & 15)) * 128 + ((lane >> 4) << 4));
    const uint32_t b_row  = (uint32_t)(wn * 64 + (lane & 7) + ((lane >> 4) << 3));
    const uint32_t b_coff = (uint32_t)(((lane >> 3) & 1) << 4);

    for (int ch = 0; ch < 8; ++ch) {
        const int k0 = ch << 6;
#pragma unroll
        for (int it = tid; it < 1024; it += 256) {
            const int r = it >> 3, p = it & 7;
            const uint32_t off = sw128((uint32_t)(r * 128 + p * 16));
            const size_t ga = (size_t)(m0 + r) * K + k0 + p * 8;
            *(uint4*)(smem + GSM_AH + off) = *(const uint4*)(g_xhi + ga);
            *(uint4*)(smem + GSM_AL + off) = *(const uint4*)(g_xlo + ga);
            const size_t gb = (size_t)(n0 + r) * K + k0 + p * 8;
            *(uint4*)(smem + GSM_BH + off) = *(const uint4*)(g_wqt_hi + gb);
            *(uint4*)(smem + GSM_BL + off) = *(const uint4*)(g_wqt_lo + gb);
        }
        __syncthreads();

#pragma unroll
        for (int ks = 0; ks < 4; ++ks) {
            const uint32_t kof = (uint32_t)(ks * 32);
            uint32_t ah0[4], ah1[4], al0[4], al1[4];
            ldsm4(ah0[0], ah0[1], ah0[2], ah0[3], sb + GSM_AH + sw128(a_off0 + kof));
            ldsm4(ah1[0], ah1[1], ah1[2], ah1[3], sb + GSM_AH + sw128(a_off1 + kof));
            ldsm4(al0[0], al0[1], al0[2], al0[3], sb + GSM_AL + sw128(a_off0 + kof));
            ldsm4(al1[0], al1[1], al1[2], al1[3], sb + GSM_AL + sw128(a_off1 + kof));
#pragma unroll
            for (int p = 0; p < 4; ++p) {
                uint32_t bh[4], bl[4];
                const uint32_t boff = (uint32_t)((b_row + p * 16) * 128) + b_coff + kof;
                ldsm4(bh[0], bh[1], bh[2], bh[3], sb + GSM_BH + sw128(boff));
                ldsm4(bl[0], bl[1], bl[2], bl[3], sb + GSM_BL + sw128(boff));
                mma16816(c[0][2 * p],     ah0, bh);      mma16816(c[1][2 * p],     ah1, bh);
                mma16816(c[0][2 * p + 1], ah0, bh + 2);  mma16816(c[1][2 * p + 1], ah1, bh + 2);
                mma16816(c[0][2 * p],     ah0, bl);      mma16816(c[1][2 * p],     ah1, bl);
                mma16816(c[0][2 * p + 1], ah0, bl + 2);  mma16816(c[1][2 * p + 1], ah1, bl + 2);
                mma16816(c[0][2 * p],     al0, bh);      mma16816(c[1][2 * p],     al1, bh);
                mma16816(c[0][2 * p + 1], al0, bh + 2);  mma16816(c[1][2 * p + 1], al1, bh + 2);
            }
        }
        __syncthreads();
    }

#pragma unroll
    for (int mt = 0; mt < 2; ++mt) {
#pragma unroll
        for (int rh = 0; rh < 2; ++rh) {
            const int r = m0 + wm * 32 + mt * 16 + (lane >> 2) + rh * 8;
            float vals[16];
            float s = 0.f, s2 = 0.f;
#pragma unroll
            for (int nt = 0; nt < 8; ++nt)
#pragma unroll
                for (int jj = 0; jj < 2; ++jj) {
                    const int col = n0 + wn * 64 + nt * 8 + (lane & 3) * 2 + jj;
                    float v = c[mt][nt][rh * 2 + jj] + __ldg(bias + col);
                    vals[nt * 2 + jj] = v;
                    s += v; s2 += v * v;
                }
            s  += __shfl_xor_sync(0xffffffffu, s, 1);
            s  += __shfl_xor_sync(0xffffffffu, s, 2);
            s2 += __shfl_xor_sync(0xffffffffu, s2, 1);
            s2 += __shfl_xor_sync(0xffffffffu, s2, 2);
            const float mu  = s * (1.f / 64.f);
            const float var = s2 * (1.f / 64.f) - mu * mu;
            const float inv = rsqrtf(var + LN_EPS);
            const int slot = (n0 + wn * 64) >> 6;
#pragma unroll
            for (int nt = 0; nt < 8; ++nt) {
                const int kd = nt * 8 + (lane & 3) * 2;
                __nv_bfloat16 h0, l0, h1, l1;
                float o0 = (vals[nt * 2]     - mu) * inv * __ldg(gamma + kd)     + __ldg(beta + kd);
                float o1 = (vals[nt * 2 + 1] - mu) * inv * __ldg(gamma + kd + 1) + __ldg(beta + kd + 1);
                split_bf16(o0, h0, l0); split_bf16(o1, h1, l1);
                const size_t qi = ((size_t)r * NQn + slot) * KDn + kd;
                __nv_bfloat162 ph; ph.x = h0; ph.y = h1;
                __nv_bfloat162 pl; pl.x = l0; pl.y = l1;
                *(__nv_bfloat162*)(g_qhi + qi) = ph;
                *(__nv_bfloat162*)(g_qlo + qi) = pl;
            }
        }
    }
}

// ---------------------------------------------------------------------------
// attn_part: (64-token tile, slot, key-part of 512). 8 chunks of 64 keys.
// Fragment-register top-8: each thread tracks two rows' top-8 (packed int,
// IMNMX only) directly from MMA accumulators. No score smem, 1 barrier/chunk.
// smem: Q 16KB | K 16KB = 32KB.
// ---------------------------------------------------------------------------
#define ASM_QH 0
#define ASM_QL 8192
#define ASM_KH 16384
#define ASM_KL 24576
#define ATTN_SMEM 32768

__global__ __launch_bounds__(256, 3) void attn_part_kernel()
{
    extern __shared__ char smem[];
    const uint32_t sb = smem_u32(smem);
    const int tid  = threadIdx.x;
    const int lane = tid & 31;
    const int w    = tid >> 5;
    const int wm   = w & 3;
    const int wn   = w >> 2;
    const int slot = blockIdx.y;
    const int t0   = blockIdx.x << 6;
    const int part = blockIdx.z;
    const int kbase = part << 9;            // 512 keys per part

    // Q tile: 64 tokens x 64 bf16 hi/lo
#pragma unroll
    for (int it = tid; it < 512; it += 256) {
        const int r = it >> 3, p = it & 7;
        const uint32_t off = sw128((uint32_t)(r * 128 + p * 16));
        const size_t g = ((size_t)(t0 + r) * NQn + slot) * KDn + p * 8;
        *(uint4*)(smem + ASM_QH + off) = *(const uint4*)(g_qhi + g);
        *(uint4*)(smem + ASM_QL + off) = *(const uint4*)(g_qlo + g);
    }

    const __nv_bfloat16* kbh = g_khi + ((size_t)(slot & 7) * NKn + kbase) * KDn;
    const __nv_bfloat16* kbl = g_klo + ((size_t)(slot & 7) * NKn + kbase) * KDn;

    const uint32_t a_off = (uint32_t)((wm * 16 + (lane & 15)) * 128 + ((lane >> 4) << 4));
    const uint32_t b_row = (uint32_t)(wn * 32 + (lane & 7) + ((lane >> 4) << 3));
    const uint32_t b_coff = (uint32_t)(((lane >> 3) & 1) << 4);
    // column base for this thread's fragment scores
    const int colbase = kbase + wn * 32 + (lane & 3) * 2;

    int tvA[8], tvB[8];
#pragma unroll
    for (int i = 0; i < 8; ++i) { tvA[i] = (int)0x80000000; tvB[i] = (int)0x80000000; }

    for (int ch = 0; ch < 8; ++ch) {
        __syncthreads();   // prior chunk's ldsm reads done before overwrite
#pragma unroll
        for (int it = tid; it < 512; it += 256) {
            const int r = it >> 3, p = it & 7;
            const uint32_t off = sw128((uint32_t)(r * 128 + p * 16));
            const size_t g = (size_t)(ch * 64 + r) * KDn + p * 8;
            *(uint4*)(smem + ASM_KH + off) = *(const uint4*)(kbh + g);
            *(uint4*)(smem + ASM_KL + off) = *(const uint4*)(kbl + g);
        }
        __syncthreads();

        float c[4][4];
#pragma unroll
        for (int nt = 0; nt < 4; ++nt)
#pragma unroll
            for (int j = 0; j < 4; ++j) c[nt][j] = 0.f;

#pragma unroll
        for (int ks = 0; ks < 4; ++ks) {
            const uint32_t kof = (uint32_t)(ks * 32);
            uint32_t ah[4], al[4];
            ldsm4(ah[0], ah[1], ah[2], ah[3], sb + ASM_QH + sw128(a_off + kof));
            ldsm4(al[0], al[1], al[2], al[3], sb + ASM_QL + sw128(a_off + kof));
#pragma unroll
            for (int p = 0; p < 2; ++p) {
                uint32_t bh[4], bl[4];
                const uint32_t boff = (uint32_t)((b_row + p * 16) * 128) + b_coff + kof;
                ldsm4(bh[0], bh[1], bh[2], bh[3], sb + ASM_KH + sw128(boff));
                ldsm4(bl[0], bl[1], bl[2], bl[3], sb + ASM_KL + sw128(boff));
                mma16816(c[2 * p],     ah, bh);
                mma16816(c[2 * p + 1], ah, bh + 2);
                mma16816(c[2 * p],     ah, bl);
                mma16816(c[2 * p + 1], ah, bl + 2);
                mma16816(c[2 * p],     al, bh);
                mma16816(c[2 * p + 1], al, bh + 2);
            }
        }

        // in-register scan: row A (j=0,1), row B (j=2,3); cols nt*8 in fragment
        const int gi0 = colbase + ch * 64;
        {
            float mA = fmaxf(fmaxf(fmaxf(c[0][0], c[0][1]), fmaxf(c[1][0], c[1][1])),
                             fmaxf(fmaxf(c[2][0], c[2][1]), fmaxf(c[3][0], c[3][1])));
            if (packsc(mA, 0) > tvA[7]) {
#pragma unroll
                for (int nt = 0; nt < 4; ++nt) {
                    insp(packsc(c[nt][0], gi0 + nt * 8),     tvA);
                    insp(packsc(c[nt][1], gi0 + nt * 8 + 1), tvA);
                }
            }
            float mB = fmaxf(fmaxf(fmaxf(c[0][2], c[0][3]), fmaxf(c[1][2], c[1][3])),
                             fmaxf(fmaxf(c[2][2], c[2][3]), fmaxf(c[3][2], c[3][3])));
            if (packsc(mB, 0) > tvB[7]) {
#pragma unroll
                for (int nt = 0; nt < 4; ++nt) {
                    insp(packsc(c[nt][2], gi0 + nt * 8),     tvB);
                    insp(packsc(c[nt][3], gi0 + nt * 8 + 1), tvB);
                }
            }
        }
    }

    // stage per-thread sorted runs: sub-run id = wn*4 + (lane&3), 8 runs/row
    {
        const int sub = wn * 4 + (lane & 3);
        const int rA = t0 + wm * 16 + (lane >> 2);
        const size_t rowA = (size_t)rA * NQn + slot;
        int* dvA = g_topp + rowA * 256 + part * 64 + sub * 8;
#pragma unroll
        for (int i = 0; i < 8; ++i) dvA[i] = tvA[i];
        const size_t rowB = (size_t)(rA + 8) * NQn + slot;
        int* dvB = g_topp + rowB * 256 + part * 64 + sub * 8;
#pragma unroll
        for (int i = 0; i < 8; ++i) dvB[i] = tvB[i];
    }
}

// ---------------------------------------------------------------------------
// merge: 8 threads/row. Stage 1: each merges 4 sorted runs of 8 -> top-8.
// Stage 2: first thread of the 8 merges the 8 partials, decodes, softmax.
// ---------------------------------------------------------------------------
__global__ __launch_bounds__(256) void attn_merge_kernel()
{
    __shared__ int stg[32][65];            // 32 rows/block x 8 runs x 8 (+pad)
    const int g = blockIdx.x * 256 + threadIdx.x;
    const int row = g >> 3;
    const int oct = g & 7;
    const int lrow = threadIdx.x >> 3;
    if (row >= NROWS) return;

    // Stage 1: merge 4 sorted descending runs of 8 -> top-8
    {
        const int* src = g_topp + (size_t)row * 256 + oct * 32;
        int ptr[4] = {0, 0, 0, 0};
        int out[8];
#pragma unroll
        for (int s = 0; s < 8; ++s) {
            int best = (int)0x80000000, br = 0;
#pragma unroll
            for (int run = 0; run < 4; ++run) {
                const int cv = (ptr[run] < 8) ? src[run * 8 + ptr[run]] : (int)0x80000000;
                if (cv > best) { best = cv; br = run; }
            }
            out[s] = best; ptr[br]++;
        }
#pragma unroll
        for (int i = 0; i < 8; ++i) stg[lrow][oct * 8 + i] = out[i];
    }
    __syncthreads();

    if (oct == 0) {
        int ptr[8] = {0, 0, 0, 0, 0, 0, 0, 0};
        int fin[8];
#pragma unroll
        for (int s = 0; s < 8; ++s) {
            int best = (int)0x80000000, br = 0;
#pragma unroll
            for (int run = 0; run < 8; ++run) {
                const int cv = (ptr[run] < 8) ? stg[lrow][run * 8 + ptr[run]] : (int)0x80000000;
                if (cv > best) { best = cv; br = run; }
            }
            fin[s] = best; ptr[br]++;
        }
        // decode + softmax
        float sv[8]; int si[8];
#pragma unroll
        for (int i = 0; i < 8; ++i) {
            si[i] = 2047 - (fin[i] & 2047);
            sv[i] = (float)(fin[i] >> 11) * (1.f / 32768.f);
        }
        const float mx = sv[0];
        float pr[8], denom = 0.f;
#pragma unroll
        for (int i = 0; i < 8; ++i) { pr[i] = expf(sv[i] - mx); denom += pr[i]; }
        const float inv = 1.f / denom;
#pragma unroll
        for (int i = 0; i < 8; ++i) { g_pw[(size_t)row * 8 + i] = pr[i] * inv; g_pidx[(size_t)row * 8 + i] = si[i]; }
    }
}

// ---------------------------------------------------------------------------
// gather: 4 threads per row x 32 dims; V gather -> hi/lo split output.
// ---------------------------------------------------------------------------
__global__ __launch_bounds__(256) void attn_gather_kernel(const float* __restrict__ values)
{
    const int g = blockIdx.x * 256 + threadIdx.x;
    const int row = g >> 2;
    if (row >= NROWS) return;
    const int d0 = (g & 3) * 32;
    const int slot = row & 15;

    float pr[8]; int ir[8];
#pragma unroll
    for (int i = 0; i < 8; ++i) { pr[i] = g_pw[(size_t)row * 8 + i]; ir[i] = g_pidx[(size_t)row * 8 + i]; }

    const float* vb = values + (size_t)(slot & 7) * NKn * VDn + d0;
    __nv_bfloat16* oh = g_atthi + (size_t)row * VDn + d0;
    __nv_bfloat16* ol = g_attlo + (size_t)row * VDn + d0;
#pragma unroll
    for (int dd = 0; dd < 32; dd += 4) {
        float4 acc = make_float4(0.f, 0.f, 0.f, 0.f);
#pragma unroll
        for (int i = 0; i < 8; ++i) {
            const float4 vv = *(const float4*)(vb + (size_t)ir[i] * VDn + dd);
            acc.x += pr[i] * vv.x; acc.y += pr[i] * vv.y;
            acc.z += pr[i] * vv.z; acc.w += pr[i] * vv.w;
        }
        __nv_bfloat16 h, l;
        split_bf16(acc.x, h, l); oh[dd]     = h; ol[dd]     = l;
        split_bf16(acc.y, h, l); oh[dd + 1] = h; ol[dd + 1] = l;
        split_bf16(acc.z, h, l); oh[dd + 2] = h; ol[dd + 2] = l;
        split_bf16(acc.w, h, l); oh[dd + 3] = h; ol[dd + 3] = l;
    }
}

// ---------------------------------------------------------------------------
// gemm_out: out = [att | q] @ [Wmem ; Wrm]^T + brm, REMAP. K=192.
// ---------------------------------------------------------------------------
__global__ __launch_bounds__(256) void gemm_out_kernel(float* __restrict__ C)
{
    extern __shared__ char smem[];
    const uint32_t sb = smem_u32(smem);
    const int tid  = threadIdx.x;
    const int lane = tid & 31;
    const int w    = tid >> 5;
    const int wm   = w & 3;
    const int wn   = w >> 2;
    const int m0   = blockIdx.y << 7;
    const int n0   = blockIdx.x << 7;

    float c[2][8][4];
#pragma unroll
    for (int mt = 0; mt < 2; ++mt)
#pragma unroll
        for (int nt = 0; nt < 8; ++nt)
#pragma unroll
            for (int j = 0; j < 4; ++j) c[mt][nt][j] = 0.f;

    const uint32_t a_off0 = (uint32_t)((wm * 32 + (lane & 15)) * 128 + ((lane >> 4) << 4));
    const uint32_t a_off1 = (uint32_t)((wm * 32 + 16 + (lane & 15)) * 128 + ((lane >> 4) << 4));
    const uint32_t b_row  = (uint32_t)(wn * 64 + (lane & 7) + ((lane >> 4) << 3));
    const uint32_t b_coff = (uint32_t)(((lane >> 3) & 1) << 4);

    for (int ch = 0; ch < 3; ++ch) {
#pragma unroll
        for (int it = tid; it < 1024; it += 256) {
            const int r = it >> 3, p = it & 7;
            const uint32_t off = sw128((uint32_t)(r * 128 + p * 16));
            if (ch < 2) {
                const size_t ga = (size_t)(m0 + r) * VDn + (ch << 6) + p * 8;
                *(uint4*)(smem + GSM_AH + off) = *(const uint4*)(g_atthi + ga);
                *(uint4*)(smem + GSM_AL + off) = *(const uint4*)(g_attlo + ga);
                const size_t gb = (size_t)(n0 + r) * VDn + (ch << 6) + p * 8;
                *(uint4*)(smem + GSM_BH + off) = *(const uint4*)(g_wmemt_hi + gb);
                *(uint4*)(smem + GSM_BL + off) = *(const uint4*)(g_wmemt_lo + gb);
            } else {
                const size_t ga = (size_t)(m0 + r) * KDn + p * 8;
                *(uint4*)(smem + GSM_AH + off) = *(const uint4*)(g_qhi + ga);
                *(uint4*)(smem + GSM_AL + off) = *(const uint4*)(g_qlo + ga);
                const size_t gb = (size_t)(n0 + r) * KDn + p * 8;
                *(uint4*)(smem + GSM_BH + off) = *(const uint4*)(g_wrmt_hi + gb);
                *(uint4*)(smem + GSM_BL + off) = *(const uint4*)(g_wrmt_lo + gb);
            }
        }
        __syncthreads();

#pragma unroll
        for (int ks = 0; ks < 4; ++ks) {
            const uint32_t kof = (uint32_t)(ks * 32);
            uint32_t ah0[4], ah1[4], al0[4], al1[4];
            ldsm4(ah0[0], ah0[1], ah0[2], ah0[3], sb + GSM_AH + sw128(a_off0 + kof));
            ldsm4(ah1[0], ah1[1], ah1[2], ah1[3], sb + GSM_AH + sw128(a_off1 + kof));
            ldsm4(al0[0], al0[1], al0[2], al0[3], sb + GSM_AL + sw128(a_off0 + kof));
            ldsm4(al1[0], al1[1], al1[2], al1[3], sb + GSM_AL + sw128(a_off1 + kof));
#pragma unroll
            for (int p = 0; p < 4; ++p) {
                uint32_t bh[4], bl[4];
                const uint32_t boff = (uint32_t)((b_row + p * 16) * 128) + b_coff + kof;
                ldsm4(bh[0], bh[1], bh[2], bh[3], sb + GSM_BH + sw128(boff));
                ldsm4(bl[0], bl[1], bl[2], bl[3], sb + GSM_BL + sw128(boff));
                mma16816(c[0][2 * p],     ah0, bh);      mma16816(c[1][2 * p],     ah1, bh);
                mma16816(c[0][2 * p + 1], ah0, bh + 2);  mma16816(c[1][2 * p + 1], ah1, bh + 2);
                mma16816(c[0][2 * p],     ah0, bl);      mma16816(c[1][2 * p],     ah1, bl);
                mma16816(c[0][2 * p + 1], ah0, bl + 2);  mma16816(c[1][2 * p + 1], ah1, bl + 2);
                mma16816(c[0][2 * p],     al0, bh);      mma16816(c[1][2 * p],     al1, bh);
                mma16816(c[0][2 * p + 1], al0, bh + 2);  mma16816(c[1][2 * p + 1], al1, bh + 2);
            }
        }
        __syncthreads();
    }

#pragma unroll
    for (int mt = 0; mt < 2; ++mt) {
#pragma unroll
        for (int nt = 0; nt < 8; ++nt) {
#pragma unroll
            for (int j = 0; j < 4; ++j) {
                const int r   = m0 + wm * 32 + mt * 16 + (lane >> 2) + (j >= 2 ? 8 : 0);
                const int col = n0 + wn * 64 + nt * 8 + (lane & 3) * 2 + (j & 1);
                const float v = c[mt][nt][j] + g_brm[col];
                const int token = r >> 4;
                const int slot  = r & 15;
                const size_t base = (slot < NSn) ? 0 : (size_t)BS_TOK * NSn * MEMn;
                C[base + (size_t)(token * NSn + (slot & 7)) * MEMn + col] = v;
            }
        }
    }
}

// ---------------------------------------------------------------------------
// Host launcher. attn_part at launch index 3 (the profiled launch).
// ---------------------------------------------------------------------------
extern "C" void kernel_launch(void* const* d_in, const int* in_sizes, int n_in,
                              void* d_out, int out_size)
{
    const float* x      = (const float*)d_in[0];
    const float* Wq     = (const float*)d_in[1];
    const float* bq     = (const float*)d_in[2];
    const float* ln_g   = (const float*)d_in[3];
    const float* ln_b   = (const float*)d_in[4];
    const float* keys   = (const float*)d_in[5];
    const float* values = (const float*)d_in[6];
    const float* Wres   = (const float*)d_in[7];
    const float* bres   = (const float*)d_in[8];
    const float* Wmem   = (const float*)d_in[9];
    const float* bmem   = (const float*)d_in[10];
    float* out = (float*)d_out;

    cudaFuncSetAttribute(gemm_q_kernel,    cudaFuncAttributeMaxDynamicSharedMemorySize, GEMM_SMEM);
    cudaFuncSetAttribute(gemm_out_kernel,  cudaFuncAttributeMaxDynamicSharedMemorySize, GEMM_SMEM);
    cudaFuncSetAttribute(attn_part_kernel, cudaFuncAttributeMaxDynamicSharedMemorySize, ATTN_SMEM);

    prep_weights<<<6530, 256>>>(x, Wq, Wres, Wmem, bres, bmem);
    knorm_split_kernel<<<2048, 256>>>(keys);
    gemm_q_kernel<<<dim3(8, 16), 256, GEMM_SMEM>>>(bq, ln_g, ln_b);
    attn_part_kernel<<<dim3(32, 16, 4), 256, ATTN_SMEM>>>();
    attn_merge_kernel<<<1024, 256>>>();
    attn_gather_kernel<<<512, 256>>>(values);
    gemm_out_kernel<<<dim3(4, 256), 256, GEMM_SMEM>>>(out);
}

// round 14
// speedup vs baseline: 1.0651x; 1.0651x over previous
#include <cuda_runtime.h>
#include <cuda_bf16.h>
#include <math.h>
#include <float.h>
#include <stdint.h>

#define BS_TOK 2048
#define NQn 16
#define NSn 8
#define KDn 64
#define NKn 2048
#define VDn 128
#define MEMn 512
#define LN_EPS 1e-5f
#define NROWS (BS_TOK * NQn)

// ---------------------------------------------------------------------------
// Scratch globals
// ---------------------------------------------------------------------------
__device__ __nv_bfloat16 g_xhi[BS_TOK * 512],        g_xlo[BS_TOK * 512];
__device__ __nv_bfloat16 g_wqt_hi[1024 * 512],       g_wqt_lo[1024 * 512];
__device__ __nv_bfloat16 g_qhi[NROWS * KDn],         g_qlo[NROWS * KDn];
__device__ __nv_bfloat16 g_khi[NSn * NKn * KDn],     g_klo[NSn * NKn * KDn];
__device__ __nv_bfloat16 g_wmemt_hi[MEMn * VDn],     g_wmemt_lo[MEMn * VDn];
__device__ __nv_bfloat16 g_wrmt_hi[MEMn * KDn],      g_wrmt_lo[MEMn * KDn];
__device__ float         g_brm[MEMn];
__device__ __nv_bfloat16 g_atthi[NROWS * VDn],       g_attlo[NROWS * VDn];
// attention staging: 4 parts x 4 sub-runs x 8 packed (score,idx) per row
__device__ int g_topp[(size_t)NROWS * 128];

// ---------------------------------------------------------------------------
// Helpers
// ---------------------------------------------------------------------------
__device__ __forceinline__ uint32_t smem_u32(const void* p) {
    uint32_t a;
    asm("{ .reg .u64 t; cvta.to.shared.u64 t, %1; cvt.u32.u64 %0, t; }" : "=r"(a) : "l"(p));
    return a;
}
__device__ __forceinline__ uint32_t sw128(uint32_t off) { return off ^ ((off >> 3) & 0x70); }

__device__ __forceinline__ void mma16816(float c[4], const uint32_t a[4], const uint32_t b[2])
{
    asm("mma.sync.aligned.m16n8k16.row.col.f32.bf16.bf16.f32 "
        "{%0,%1,%2,%3},{%4,%5,%6,%7},{%8,%9},{%0,%1,%2,%3};"
        : "+f"(c[0]), "+f"(c[1]), "+f"(c[2]), "+f"(c[3])
        : "r"(a[0]), "r"(a[1]), "r"(a[2]), "r"(a[3]), "r"(b[0]), "r"(b[1]));
}
__device__ __forceinline__ void ldsm4(uint32_t& r0, uint32_t& r1, uint32_t& r2, uint32_t& r3, uint32_t addr)
{
    asm volatile("ldmatrix.sync.aligned.m8n8.x4.shared.b16 {%0,%1,%2,%3}, [%4];"
                 : "=r"(r0), "=r"(r1), "=r"(r2), "=r"(r3) : "r"(addr));
}
__device__ __forceinline__ void cpa16(uint32_t s, const void* g) {
    asm volatile("cp.async.cg.shared.global [%0], [%1], 16;" :: "r"(s), "l"(g));
}
__device__ __forceinline__ void cpa_commit() { asm volatile("cp.async.commit_group;" ::: "memory"); }
template<int N> __device__ __forceinline__ void cpa_wait() {
    asm volatile("cp.async.wait_group %0;" :: "n"(N) : "memory");
}
__device__ __forceinline__ void split_bf16(float v, __nv_bfloat16& h, __nv_bfloat16& l) {
    h = __float2bfloat16(v);
    l = __float2bfloat16(v - __bfloat162float(h));
}
// |s| <= 8 guaranteed; pack monotone in s, ties -> lower idx.
__device__ __forceinline__ int packsc(float s, int idx) {
    const int q = __float2int_rn(s * 32768.f);
    return (q << 11) | (2047 - idx);
}
__device__ __forceinline__ void insp(int s, int tv[8]) {
#pragma unroll
    for (int i = 0; i < 8; ++i) {
        const int lo = min(tv[i], s);
        tv[i] = max(tv[i], s);
        s = lo;
    }
}

// ---------------------------------------------------------------------------
// Prep (x split, Wmem/Wrm/brm); Wq handled by tiled transpose kernel
// ---------------------------------------------------------------------------
__global__ void prep_weights(const float* __restrict__ x,
                             const float* __restrict__ Wres, const float* __restrict__ Wmem,
                             const float* __restrict__ bres, const float* __restrict__ bmem)
{
    const int b = blockIdx.x;
    const int tid = threadIdx.x;
    __nv_bfloat16 h, l;
    if (b < 4096) {
        const int i = b * 256 + tid;
        split_bf16(x[i], h, l);
        g_xhi[i] = h; g_xlo[i] = l;
    } else if (b < 4352) {                            // Wmem: K=128, N=512
        const int i = (b - 4096) * 256 + tid;
        const int k = i >> 9, n = i & 511;
        split_bf16(Wmem[i], h, l);
        g_wmemt_hi[(size_t)n * 128 + k] = h;
        g_wmemt_lo[(size_t)n * 128 + k] = l;
    } else if (b < 4480) {                            // Wrm = Wres@Wmem: 64 x 512
        const int i = (b - 4352) * 256 + tid;
        const int m = i >> 9, n = i & 511;
        float acc = 0.f;
#pragma unroll 8
        for (int k = 0; k < VDn; ++k)
            acc += Wres[m * VDn + k] * Wmem[k * MEMn + n];
        split_bf16(acc, h, l);
        g_wrmt_hi[(size_t)n * KDn + m] = h;
        g_wrmt_lo[(size_t)n * KDn + m] = l;
    } else if (b < 4482) {
        const int n = (b - 4480) * 256 + tid;
        float acc = bmem[n];
#pragma unroll 8
        for (int k = 0; k < VDn; ++k)
            acc += bres[k] * Wmem[k * MEMn + n];
        g_brm[n] = acc;
    }
}

// Tiled transpose-split for Wq: in (512 x 1024) k-major -> out (1024 x 512)
__global__ __launch_bounds__(256) void tsplit_wq_kernel(const float* __restrict__ Wq)
{
    __shared__ float tile[32][33];
    const int n0 = blockIdx.x << 5;
    const int k0 = blockIdx.y << 5;
    const int tx = threadIdx.x & 31;
    const int ty = threadIdx.x >> 5;      // 0..7
#pragma unroll
    for (int i = 0; i < 4; ++i)
        tile[ty + 8 * i][tx] = Wq[(size_t)(k0 + ty + 8 * i) * 1024 + n0 + tx];
    __syncthreads();
#pragma unroll
    for (int i = 0; i < 4; ++i) {
        __nv_bfloat16 h, l;
        split_bf16(tile[tx][ty + 8 * i], h, l);
        const size_t o = (size_t)(n0 + ty + 8 * i) * 512 + k0 + tx;
        g_wqt_hi[o] = h; g_wqt_lo[o] = l;
    }
}

__global__ void knorm_split_kernel(const float* __restrict__ keys)
{
    const int warp = (blockIdx.x * blockDim.x + threadIdx.x) >> 5;
    const int lane = threadIdx.x & 31;
    if (warp >= NSn * NKn) return;
    const float* src = keys + (size_t)warp * KDn;
    float v0 = src[lane], v1 = src[lane + 32];
    float sq = v0 * v0 + v1 * v1;
#pragma unroll
    for (int o = 16; o > 0; o >>= 1) sq += __shfl_xor_sync(0xffffffffu, sq, o);
    const float scale = rsqrtf(sq);
    __nv_bfloat16 h, l;
    split_bf16(v0 * scale, h, l); g_khi[(size_t)warp * KDn + lane] = h;      g_klo[(size_t)warp * KDn + lane] = l;
    split_bf16(v1 * scale, h, l); g_khi[(size_t)warp * KDn + lane + 32] = h; g_klo[(size_t)warp * KDn + lane + 32] = l;
}

// ---------------------------------------------------------------------------
// gemm_q: q = LN(x @ Wq^T' + bq), cp.async DOUBLE-BUFFERED (grid-starved
// kernel: 128 CTAs < 148 SMs, so 128KB smem costs nothing). LN epilogue.
// ---------------------------------------------------------------------------
#define GST 65536
#define GSM_AH 0
#define GSM_AL 16384
#define GSM_BH 32768
#define GSM_BL 49152
#define GEMMQ_SMEM (2 * GST)
#define GEMM_SMEM 65536

__global__ __launch_bounds__(256) void gemm_q_kernel(const float* __restrict__ bias,
                                                     const float* __restrict__ gamma,
                                                     const float* __restrict__ beta)
{
    extern __shared__ char smem[];
    const uint32_t sb = smem_u32(smem);
    const int tid  = threadIdx.x;
    const int lane = tid & 31;
    const int w    = tid >> 5;
    const int wm   = w & 3;
    const int wn   = w >> 2;
    const int m0   = blockIdx.y << 7;
    const int n0   = blockIdx.x << 7;
    const int K    = 512;

    float c[2][8][4];
#pragma unroll
    for (int mt = 0; mt < 2; ++mt)
#pragma unroll
        for (int nt = 0; nt < 8; ++nt)
#pragma unroll
            for (int j = 0; j < 4; ++j) c[mt][nt][j] = 0.f;

    const uint32_t a_off0 = (uint32_t)((wm * 32 + (lane & 15)) * 128 + ((lane >> 4) << 4));
    const uint32_t a_off1 = (uint32_t)((wm * 32 + 16 + (lane & 15)) * 128 + ((lane >> 4) << 4));
    const uint32_t b_row  = (uint32_t)(wn * 64 + (lane & 7) + ((lane >> 4) << 3));
    const uint32_t b_coff = (uint32_t)(((lane >> 3) & 1) << 4);

    auto load_tiles = [&](int stage, int ch) {
        const int k0 = ch << 6;
        const uint32_t stg = sb + stage * GST;
#pragma unroll
        for (int it = tid; it < 1024; it += 256) {
            const int r = it >> 3, p = it & 7;
            const uint32_t off = sw128((uint32_t)(r * 128 + p * 16));
            const size_t ga = (size_t)(m0 + r) * K + k0 + p * 8;
            cpa16(stg + GSM_AH + off, g_xhi + ga);
            cpa16(stg + GSM_AL + off, g_xlo + ga);
            const size_t gb = (size_t)(n0 + r) * K + k0 + p * 8;
            cpa16(stg + GSM_BH + off, g_wqt_hi + gb);
            cpa16(stg + GSM_BL + off, g_wqt_lo + gb);
        }
        cpa_commit();
    };

    load_tiles(0, 0);
    for (int ch = 0; ch < 8; ++ch) {
        if (ch + 1 < 8) { load_tiles((ch + 1) & 1, ch + 1); cpa_wait<1>(); }
        else            { cpa_wait<0>(); }
        __syncthreads();

        const uint32_t stg = sb + (ch & 1) * GST;
#pragma unroll
        for (int ks = 0; ks < 4; ++ks) {
            const uint32_t kof = (uint32_t)(ks * 32);
            uint32_t ah0[4], ah1[4], al0[4], al1[4];
            ldsm4(ah0[0], ah0[1], ah0[2], ah0[3], stg + GSM_AH + sw128(a_off0 + kof));
            ldsm4(ah1[0], ah1[1], ah1[2], ah1[3], stg + GSM_AH + sw128(a_off1 + kof));
            ldsm4(al0[0], al0[1], al0[2], al0[3], stg + GSM_AL + sw128(a_off0 + kof));
            ldsm4(al1[0], al1[1], al1[2], al1[3], stg + GSM_AL + sw128(a_off1 + kof));
#pragma unroll
            for (int p = 0; p < 4; ++p) {
                uint32_t bh[4], bl[4];
                const uint32_t boff = (uint32_t)((b_row + p * 16) * 128) + b_coff + kof;
                ldsm4(bh[0], bh[1], bh[2], bh[3], stg + GSM_BH + sw128(boff));
                ldsm4(bl[0], bl[1], bl[2], bl[3], stg + GSM_BL + sw128(boff));
                mma16816(c[0][2 * p],     ah0, bh);      mma16816(c[1][2 * p],     ah1, bh);
                mma16816(c[0][2 * p + 1], ah0, bh + 2);  mma16816(c[1][2 * p + 1], ah1, bh + 2);
                mma16816(c[0][2 * p],     ah0, bl);      mma16816(c[1][2 * p],     ah1, bl);
                mma16816(c[0][2 * p + 1], ah0, bl + 2);  mma16816(c[1][2 * p + 1], ah1, bl + 2);
                mma16816(c[0][2 * p],     al0, bh);      mma16816(c[1][2 * p],     al1, bh);
                mma16816(c[0][2 * p + 1], al0, bh + 2);  mma16816(c[1][2 * p + 1], al1, bh + 2);
            }
        }
        __syncthreads();   // MMA reads done before next cp.async overwrites
    }

    // Fused LayerNorm per 64-col slot
#pragma unroll
    for (int mt = 0; mt < 2; ++mt) {
#pragma unroll
        for (int rh = 0; rh < 2; ++rh) {
            const int r = m0 + wm * 32 + mt * 16 + (lane >> 2) + rh * 8;
            float vals[16];
            float s = 0.f, s2 = 0.f;
#pragma unroll
            for (int nt = 0; nt < 8; ++nt)
#pragma unroll
                for (int jj = 0; jj < 2; ++jj) {
                    const int col = n0 + wn * 64 + nt * 8 + (lane & 3) * 2 + jj;
                    float v = c[mt][nt][rh * 2 + jj] + __ldg(bias + col);
                    vals[nt * 2 + jj] = v;
                    s += v; s2 += v * v;
                }
            s  += __shfl_xor_sync(0xffffffffu, s, 1);
            s  += __shfl_xor_sync(0xffffffffu, s, 2);
            s2 += __shfl_xor_sync(0xffffffffu, s2, 1);
            s2 += __shfl_xor_sync(0xffffffffu, s2, 2);
            const float mu  = s * (1.f / 64.f);
            const float var = s2 * (1.f / 64.f) - mu * mu;
            const float inv = rsqrtf(var + LN_EPS);
            const int slot = (n0 + wn * 64) >> 6;
#pragma unroll
            for (int nt = 0; nt < 8; ++nt) {
                const int kd = nt * 8 + (lane & 3) * 2;
                __nv_bfloat16 h0, l0, h1, l1;
                float o0 = (vals[nt * 2]     - mu) * inv * __ldg(gamma + kd)     + __ldg(beta + kd);
                float o1 = (vals[nt * 2 + 1] - mu) * inv * __ldg(gamma + kd + 1) + __ldg(beta + kd + 1);
                split_bf16(o0, h0, l0); split_bf16(o1, h1, l1);
                const size_t qi = ((size_t)r * NQn + slot) * KDn + kd;
                __nv_bfloat162 ph; ph.x = h0; ph.y = h1;
                __nv_bfloat162 pl; pl.x = l0; pl.y = l1;
                *(__nv_bfloat162*)(g_qhi + qi) = ph;
                *(__nv_bfloat162*)(g_qlo + qi) = pl;
            }
        }
    }
}

// ---------------------------------------------------------------------------
// attn_part (R12 config): (64-token tile, slot, key-part of 512), 8 chunks,
// smem score tile + packed IMNMX top-8 (4 threads/token x 16 keys).
// ---------------------------------------------------------------------------
#define ASM_QH 0
#define ASM_QL 8192
#define ASM_KH 16384
#define ASM_KL 24576
#define ASM_SC 32768
#define SC_PITCH 68
#define ATTN_SMEM (32768 + 64 * SC_PITCH * 4)

__global__ __launch_bounds__(256, 3) void attn_part_kernel()
{
    extern __shared__ char smem[];
    float* sc = (float*)(smem + ASM_SC);
    const uint32_t sb = smem_u32(smem);
    const int tid  = threadIdx.x;
    const int lane = tid & 31;
    const int w    = tid >> 5;
    const int wm   = w & 3;
    const int wn   = w >> 2;
    const int slot = blockIdx.y;
    const int t0   = blockIdx.x << 6;
    const int part = blockIdx.z;
    const int kbase = part << 9;

#pragma unroll
    for (int it = tid; it < 512; it += 256) {
        const int r = it >> 3, p = it & 7;
        const uint32_t off = sw128((uint32_t)(r * 128 + p * 16));
        const size_t g = ((size_t)(t0 + r) * NQn + slot) * KDn + p * 8;
        *(uint4*)(smem + ASM_QH + off) = *(const uint4*)(g_qhi + g);
        *(uint4*)(smem + ASM_QL + off) = *(const uint4*)(g_qlo + g);
    }

    const __nv_bfloat16* kbh = g_khi + ((size_t)(slot & 7) * NKn + kbase) * KDn;
    const __nv_bfloat16* kbl = g_klo + ((size_t)(slot & 7) * NKn + kbase) * KDn;

    const uint32_t a_off = (uint32_t)((wm * 16 + (lane & 15)) * 128 + ((lane >> 4) << 4));
    const uint32_t b_row = (uint32_t)(wn * 32 + (lane & 7) + ((lane >> 4) << 3));
    const uint32_t b_coff = (uint32_t)(((lane >> 3) & 1) << 4);

    int tv[8];
#pragma unroll
    for (int i = 0; i < 8; ++i) tv[i] = (int)0x80000000;

    for (int ch = 0; ch < 8; ++ch) {
#pragma unroll
        for (int it = tid; it < 512; it += 256) {
            const int r = it >> 3, p = it & 7;
            const uint32_t off = sw128((uint32_t)(r * 128 + p * 16));
            const size_t g = (size_t)(ch * 64 + r) * KDn + p * 8;
            *(uint4*)(smem + ASM_KH + off) = *(const uint4*)(kbh + g);
            *(uint4*)(smem + ASM_KL + off) = *(const uint4*)(kbl + g);
        }
        __syncthreads();

        float c[4][4];
#pragma unroll
        for (int nt = 0; nt < 4; ++nt)
#pragma unroll
            for (int j = 0; j < 4; ++j) c[nt][j] = 0.f;

#pragma unroll
        for (int ks = 0; ks < 4; ++ks) {
            const uint32_t kof = (uint32_t)(ks * 32);
            uint32_t ah[4], al[4];
            ldsm4(ah[0], ah[1], ah[2], ah[3], sb + ASM_QH + sw128(a_off + kof));
            ldsm4(al[0], al[1], al[2], al[3], sb + ASM_QL + sw128(a_off + kof));
#pragma unroll
            for (int p = 0; p < 2; ++p) {
                uint32_t bh[4], bl[4];
                const uint32_t boff = (uint32_t)((b_row + p * 16) * 128) + b_coff + kof;
                ldsm4(bh[0], bh[1], bh[2], bh[3], sb + ASM_KH + sw128(boff));
                ldsm4(bl[0], bl[1], bl[2], bl[3], sb + ASM_KL + sw128(boff));
                mma16816(c[2 * p],     ah, bh);
                mma16816(c[2 * p + 1], ah, bh + 2);
                mma16816(c[2 * p],     ah, bl);
                mma16816(c[2 * p + 1], ah, bl + 2);
                mma16816(c[2 * p],     al, bh);
                mma16816(c[2 * p + 1], al, bh + 2);
            }
        }

        {
            const int r = wm * 16 + (lane >> 2);
#pragma unroll
            for (int nt = 0; nt < 4; ++nt) {
                const int cb = wn * 32 + nt * 8 + (lane & 3) * 2;
                sc[r * SC_PITCH + cb]           = c[nt][0];
                sc[r * SC_PITCH + cb + 1]       = c[nt][1];
                sc[(r + 8) * SC_PITCH + cb]     = c[nt][2];
                sc[(r + 8) * SC_PITCH + cb + 1] = c[nt][3];
            }
        }
        __syncthreads();

        {
            const int t = tid >> 2, base = (tid & 3) * 16;
            const float4* rowp = (const float4*)(sc + t * SC_PITCH + base);
#pragma unroll
            for (int j4 = 0; j4 < 4; ++j4) {
                const float4 v = rowp[j4];
                const float m4 = fmaxf(fmaxf(v.x, v.y), fmaxf(v.z, v.w));
                if (packsc(m4, 0) > tv[7]) {
                    const int gi = kbase + ch * 64 + base + j4 * 4;
                    insp(packsc(v.x, gi),     tv);
                    insp(packsc(v.y, gi + 1), tv);
                    insp(packsc(v.z, gi + 2), tv);
                    insp(packsc(v.w, gi + 3), tv);
                }
            }
        }
    }

    {
        const int t = tid >> 2, sub = tid & 3;
        const size_t row = (size_t)(t0 + t) * NQn + slot;
        int* dv = g_topp + row * 128 + part * 32 + sub * 8;
#pragma unroll
        for (int i = 0; i < 8; ++i) dv[i] = tv[i];
    }
}

// ---------------------------------------------------------------------------
// Fused merge + softmax + V-gather. 4 threads/row, 64 rows/block.
// ---------------------------------------------------------------------------
__global__ __launch_bounds__(256) void attn_merge_gather(const float* __restrict__ values)
{
    __shared__ int   stg[64][33];
    __shared__ float spw[64][8];
    __shared__ int   spi[64][8];
    const int g = blockIdx.x * 256 + threadIdx.x;
    const int row = g >> 2;
    const int quarter = g & 3;
    const int lrow = threadIdx.x >> 2;
    if (row >= NROWS) return;

    // Stage 1: merge 4 sorted runs of 8 -> top-8
    {
        const int* src = g_topp + (size_t)row * 128 + quarter * 32;
        int ptr[4] = {0, 0, 0, 0};
        int out[8];
#pragma unroll
        for (int s = 0; s < 8; ++s) {
            int best = (int)0x80000000, br = 0;
#pragma unroll
            for (int run = 0; run < 4; ++run) {
                const int cv = (ptr[run] < 8) ? src[run * 8 + ptr[run]] : (int)0x80000000;
                if (cv > best) { best = cv; br = run; }
            }
            out[s] = best; ptr[br]++;
        }
#pragma unroll
        for (int i = 0; i < 8; ++i) stg[lrow][quarter * 8 + i] = out[i];
    }
    __syncthreads();

    // Stage 2: finalize on quarter 0
    if (quarter == 0) {
        int ptr[4] = {0, 0, 0, 0};
        int fin[8];
#pragma unroll
        for (int s = 0; s < 8; ++s) {
            int best = (int)0x80000000, br = 0;
#pragma unroll
            for (int run = 0; run < 4; ++run) {
                const int cv = (ptr[run] < 8) ? stg[lrow][run * 8 + ptr[run]] : (int)0x80000000;
                if (cv > best) { best = cv; br = run; }
            }
            fin[s] = best; ptr[br]++;
        }
        float sv[8];
#pragma unroll
        for (int i = 0; i < 8; ++i) {
            spi[lrow][i] = 2047 - (fin[i] & 2047);
            sv[i] = (float)(fin[i] >> 11) * (1.f / 32768.f);
        }
        const float mx = sv[0];
        float pr[8], denom = 0.f;
#pragma unroll
        for (int i = 0; i < 8; ++i) { pr[i] = expf(sv[i] - mx); denom += pr[i]; }
        const float inv = 1.f / denom;
#pragma unroll
        for (int i = 0; i < 8; ++i) spw[lrow][i] = pr[i] * inv;
    }
    __syncthreads();

    // Gather: 4 threads/row x 32 dims
    {
        const int d0 = quarter * 32;
        const int slot = row & 15;
        float pr[8]; int ir[8];
#pragma unroll
        for (int i = 0; i < 8; ++i) { pr[i] = spw[lrow][i]; ir[i] = spi[lrow][i]; }
        const float* vb = values + (size_t)(slot & 7) * NKn * VDn + d0;
        __nv_bfloat16* oh = g_atthi + (size_t)row * VDn + d0;
        __nv_bfloat16* ol = g_attlo + (size_t)row * VDn + d0;
#pragma unroll
        for (int dd = 0; dd < 32; dd += 4) {
            float4 acc = make_float4(0.f, 0.f, 0.f, 0.f);
#pragma unroll
            for (int i = 0; i < 8; ++i) {
                const float4 vv = *(const float4*)(vb + (size_t)ir[i] * VDn + dd);
                acc.x += pr[i] * vv.x; acc.y += pr[i] * vv.y;
                acc.z += pr[i] * vv.z; acc.w += pr[i] * vv.w;
            }
            __nv_bfloat16 h, l;
            split_bf16(acc.x, h, l); oh[dd]     = h; ol[dd]     = l;
            split_bf16(acc.y, h, l); oh[dd + 1] = h; ol[dd + 1] = l;
            split_bf16(acc.z, h, l); oh[dd + 2] = h; ol[dd + 2] = l;
            split_bf16(acc.w, h, l); oh[dd + 3] = h; ol[dd + 3] = l;
        }
    }
}

// ---------------------------------------------------------------------------
// gemm_out: out = [att | q] @ [Wmem ; Wrm]^T + brm, REMAP. K=192.
// ---------------------------------------------------------------------------
__global__ __launch_bounds__(256) void gemm_out_kernel(float* __restrict__ C)
{
    extern __shared__ char smem[];
    const uint32_t sb = smem_u32(smem);
    const int tid  = threadIdx.x;
    const int lane = tid & 31;
    const int w    = tid >> 5;
    const int wm   = w & 3;
    const int wn   = w >> 2;
    const int m0   = blockIdx.y << 7;
    const int n0   = blockIdx.x << 7;

    float c[2][8][4];
#pragma unroll
    for (int mt = 0; mt < 2; ++mt)
#pragma unroll
        for (int nt = 0; nt < 8; ++nt)
#pragma unroll
            for (int j = 0; j < 4; ++j) c[mt][nt][j] = 0.f;

    const uint32_t a_off0 = (uint32_t)((wm * 32 + (lane & 15)) * 128 + ((lane >> 4) << 4));
    const uint32_t a_off1 = (uint32_t)((wm * 32 + 16 + (lane & 15)) * 128 + ((lane >> 4) << 4));
    const uint32_t b_row  = (uint32_t)(wn * 64 + (lane & 7) + ((lane >> 4) << 3));
    const uint32_t b_coff = (uint32_t)(((lane >> 3) & 1) << 4);

    for (int ch = 0; ch < 3; ++ch) {
#pragma unroll
        for (int it = tid; it < 1024; it += 256) {
            const int r = it >> 3, p = it & 7;
            const uint32_t off = sw128((uint32_t)(r * 128 + p * 16));
            if (ch < 2) {
                const size_t ga = (size_t)(m0 + r) * VDn + (ch << 6) + p * 8;
                *(uint4*)(smem + GSM_AH + off) = *(const uint4*)(g_atthi + ga);
                *(uint4*)(smem + GSM_AL + off) = *(const uint4*)(g_attlo + ga);
                const size_t gb = (size_t)(n0 + r) * VDn + (ch << 6) + p * 8;
                *(uint4*)(smem + GSM_BH + off) = *(const uint4*)(g_wmemt_hi + gb);
                *(uint4*)(smem + GSM_BL + off) = *(const uint4*)(g_wmemt_lo + gb);
            } else {
                const size_t ga = (size_t)(m0 + r) * KDn + p * 8;
                *(uint4*)(smem + GSM_AH + off) = *(const uint4*)(g_qhi + ga);
                *(uint4*)(smem + GSM_AL + off) = *(const uint4*)(g_qlo + ga);
                const size_t gb = (size_t)(n0 + r) * KDn + p * 8;
                *(uint4*)(smem + GSM_BH + off) = *(const uint4*)(g_wrmt_hi + gb);
                *(uint4*)(smem + GSM_BL + off) = *(const uint4*)(g_wrmt_lo + gb);
            }
        }
        __syncthreads();

#pragma unroll
        for (int ks = 0; ks < 4; ++ks) {
            const uint32_t kof = (uint32_t)(ks * 32);
            uint32_t ah0[4], ah1[4], al0[4], al1[4];
            ldsm4(ah0[0], ah0[1], ah0[2], ah0[3], sb + GSM_AH + sw128(a_off0 + kof));
            ldsm4(ah1[0], ah1[1], ah1[2], ah1[3], sb + GSM_AH + sw128(a_off1 + kof));
            ldsm4(al0[0], al0[1], al0[2], al0[3], sb + GSM_AL + sw128(a_off0 + kof));
            ldsm4(al1[0], al1[1], al1[2], al1[3], sb + GSM_AL + sw128(a_off1 + kof));
#pragma unroll
            for (int p = 0; p < 4; ++p) {
                uint32_t bh[4], bl[4];
                const uint32_t boff = (uint32_t)((b_row + p * 16) * 128) + b_coff + kof;
                ldsm4(bh[0], bh[1], bh[2], bh[3], sb + GSM_BH + sw128(boff));
                ldsm4(bl[0], bl[1], bl[2], bl[3], sb + GSM_BL + sw128(boff));
                mma16816(c[0][2 * p],     ah0, bh);      mma16816(c[1][2 * p],     ah1, bh);
                mma16816(c[0][2 * p + 1], ah0, bh + 2);  mma16816(c[1][2 * p + 1], ah1, bh + 2);
                mma16816(c[0][2 * p],     ah0, bl);      mma16816(c[1][2 * p],     ah1, bl);
                mma16816(c[0][2 * p + 1], ah0, bl + 2);  mma16816(c[1][2 * p + 1], ah1, bl + 2);
                mma16816(c[0][2 * p],     al0, bh);      mma16816(c[1][2 * p],     al1, bh);
                mma16816(c[0][2 * p + 1], al0, bh + 2);  mma16816(c[1][2 * p + 1], al1, bh + 2);
            }
        }
        __syncthreads();
    }

#pragma unroll
    for (int mt = 0; mt < 2; ++mt) {
#pragma unroll
        for (int nt = 0; nt < 8; ++nt) {
#pragma unroll
            for (int j = 0; j < 4; ++j) {
                const int r   = m0 + wm * 32 + mt * 16 + (lane >> 2) + (j >= 2 ? 8 : 0);
                const int col = n0 + wn * 64 + nt * 8 + (lane & 3) * 2 + (j & 1);
                const float v = c[mt][nt][j] + g_brm[col];
                const int token = r >> 4;
                const int slot  = r & 15;
                const size_t base = (slot < NSn) ? 0 : (size_t)BS_TOK * NSn * MEMn;
                C[base + (size_t)(token * NSn + (slot & 7)) * MEMn + col] = v;
            }
        }
    }
}

// ---------------------------------------------------------------------------
// Host launcher. gemm_q at launch index 3 (the profiled launch this round).
// ---------------------------------------------------------------------------
extern "C" void kernel_launch(void* const* d_in, const int* in_sizes, int n_in,
                              void* d_out, int out_size)
{
    const float* x      = (const float*)d_in[0];
    const float* Wq     = (const float*)d_in[1];
    const float* bq     = (const float*)d_in[2];
    const float* ln_g   = (const float*)d_in[3];
    const float* ln_b   = (const float*)d_in[4];
    const float* keys   = (const float*)d_in[5];
    const float* values = (const float*)d_in[6];
    const float* Wres   = (const float*)d_in[7];
    const float* bres   = (const float*)d_in[8];
    const float* Wmem   = (const float*)d_in[9];
    const float* bmem   = (const float*)d_in[10];
    float* out = (float*)d_out;

    cudaFuncSetAttribute(gemm_q_kernel,    cudaFuncAttributeMaxDynamicSharedMemorySize, GEMMQ_SMEM);
    cudaFuncSetAttribute(gemm_out_kernel,  cudaFuncAttributeMaxDynamicSharedMemorySize, GEMM_SMEM);
    cudaFuncSetAttribute(attn_part_kernel, cudaFuncAttributeMaxDynamicSharedMemorySize, ATTN_SMEM);

    prep_weights<<<4482, 256>>>(x, Wres, Wmem, bres, bmem);
    tsplit_wq_kernel<<<dim3(32, 16), 256>>>(Wq);
    knorm_split_kernel<<<2048, 256>>>(keys);
    gemm_q_kernel<<<dim3(8, 16), 256, GEMMQ_SMEM>>>(bq, ln_g, ln_b);   // profiled
    attn_part_kernel<<<dim3(32, 16, 4), 256, ATTN_SMEM>>>();
    attn_merge_gather<<<512, 256>>>(values);
    gemm_out_kernel<<<dim3(4, 256), 256, GEMM_SMEM>>>(out);
}

// round 15
// speedup vs baseline: 1.1230x; 1.0544x over previous
#include <cuda_runtime.h>
#include <cuda_bf16.h>
#include <math.h>
#include <float.h>
#include <stdint.h>

#define BS_TOK 2048
#define NQn 16
#define NSn 8
#define KDn 64
#define NKn 2048
#define VDn 128
#define MEMn 512
#define LN_EPS 1e-5f
#define NROWS (BS_TOK * NQn)

// ---------------------------------------------------------------------------
// Scratch globals
// ---------------------------------------------------------------------------
__device__ __nv_bfloat16 g_xhi[BS_TOK * 512],        g_xlo[BS_TOK * 512];
__device__ __nv_bfloat16 g_wqt_hi[1024 * 512],       g_wqt_lo[1024 * 512];
__device__ __nv_bfloat16 g_qhi[NROWS * KDn],         g_qlo[NROWS * KDn];
__device__ __nv_bfloat16 g_khi[NSn * NKn * KDn],     g_klo[NSn * NKn * KDn];
__device__ __nv_bfloat16 g_wmemt_hi[MEMn * VDn],     g_wmemt_lo[MEMn * VDn];
__device__ __nv_bfloat16 g_wrmt_hi[MEMn * KDn],      g_wrmt_lo[MEMn * KDn];
__device__ float         g_brm[MEMn];
__device__ __nv_bfloat16 g_atthi[NROWS * VDn],       g_attlo[NROWS * VDn];
__device__ int g_topp[(size_t)NROWS * 128];

// ---------------------------------------------------------------------------
// Helpers
// ---------------------------------------------------------------------------
__device__ __forceinline__ uint32_t smem_u32(const void* p) {
    uint32_t a;
    asm("{ .reg .u64 t; cvta.to.shared.u64 t, %1; cvt.u32.u64 %0, t; }" : "=r"(a) : "l"(p));
    return a;
}
__device__ __forceinline__ uint32_t sw128(uint32_t off) { return off ^ ((off >> 3) & 0x70); }

__device__ __forceinline__ void mma16816(float c[4], const uint32_t a[4], const uint32_t b[2])
{
    asm("mma.sync.aligned.m16n8k16.row.col.f32.bf16.bf16.f32 "
        "{%0,%1,%2,%3},{%4,%5,%6,%7},{%8,%9},{%0,%1,%2,%3};"
        : "+f"(c[0]), "+f"(c[1]), "+f"(c[2]), "+f"(c[3])
        : "r"(a[0]), "r"(a[1]), "r"(a[2]), "r"(a[3]), "r"(b[0]), "r"(b[1]));
}
__device__ __forceinline__ void ldsm4(uint32_t& r0, uint32_t& r1, uint32_t& r2, uint32_t& r3, uint32_t addr)
{
    asm volatile("ldmatrix.sync.aligned.m8n8.x4.shared.b16 {%0,%1,%2,%3}, [%4];"
                 : "=r"(r0), "=r"(r1), "=r"(r2), "=r"(r3) : "r"(addr));
}
__device__ __forceinline__ void cpa16(uint32_t s, const void* g) {
    asm volatile("cp.async.cg.shared.global [%0], [%1], 16;" :: "r"(s), "l"(g));
}
__device__ __forceinline__ void cpa_commit() { asm volatile("cp.async.commit_group;" ::: "memory"); }
template<int N> __device__ __forceinline__ void cpa_wait() {
    asm volatile("cp.async.wait_group %0;" :: "n"(N) : "memory");
}
__device__ __forceinline__ void split_bf16(float v, __nv_bfloat16& h, __nv_bfloat16& l) {
    h = __float2bfloat16(v);
    l = __float2bfloat16(v - __bfloat162float(h));
}
__device__ __forceinline__ int packsc(float s, int idx) {
    const int q = __float2int_rn(s * 32768.f);
    return (q << 11) | (2047 - idx);
}
__device__ __forceinline__ void insp(int s, int tv[8]) {
#pragma unroll
    for (int i = 0; i < 8; ++i) {
        const int lo = min(tv[i], s);
        tv[i] = max(tv[i], s);
        s = lo;
    }
}

// ---------------------------------------------------------------------------
// Prep
// ---------------------------------------------------------------------------
__global__ void prep_weights(const float* __restrict__ x,
                             const float* __restrict__ Wres, const float* __restrict__ Wmem,
                             const float* __restrict__ bres, const float* __restrict__ bmem)
{
    const int b = blockIdx.x;
    const int tid = threadIdx.x;
    __nv_bfloat16 h, l;
    if (b < 4096) {
        const int i = b * 256 + tid;
        split_bf16(x[i], h, l);
        g_xhi[i] = h; g_xlo[i] = l;
    } else if (b < 4352) {
        const int i = (b - 4096) * 256 + tid;
        const int k = i >> 9, n = i & 511;
        split_bf16(Wmem[i], h, l);
        g_wmemt_hi[(size_t)n * 128 + k] = h;
        g_wmemt_lo[(size_t)n * 128 + k] = l;
    } else if (b < 4480) {
        const int i = (b - 4352) * 256 + tid;
        const int m = i >> 9, n = i & 511;
        float acc = 0.f;
#pragma unroll 8
        for (int k = 0; k < VDn; ++k)
            acc += Wres[m * VDn + k] * Wmem[k * MEMn + n];
        split_bf16(acc, h, l);
        g_wrmt_hi[(size_t)n * KDn + m] = h;
        g_wrmt_lo[(size_t)n * KDn + m] = l;
    } else if (b < 4482) {
        const int n = (b - 4480) * 256 + tid;
        float acc = bmem[n];
#pragma unroll 8
        for (int k = 0; k < VDn; ++k)
            acc += bres[k] * Wmem[k * MEMn + n];
        g_brm[n] = acc;
    }
}

__global__ __launch_bounds__(256) void tsplit_wq_kernel(const float* __restrict__ Wq)
{
    __shared__ float tile[32][33];
    const int n0 = blockIdx.x << 5;
    const int k0 = blockIdx.y << 5;
    const int tx = threadIdx.x & 31;
    const int ty = threadIdx.x >> 5;
#pragma unroll
    for (int i = 0; i < 4; ++i)
        tile[ty + 8 * i][tx] = Wq[(size_t)(k0 + ty + 8 * i) * 1024 + n0 + tx];
    __syncthreads();
#pragma unroll
    for (int i = 0; i < 4; ++i) {
        __nv_bfloat16 h, l;
        split_bf16(tile[tx][ty + 8 * i], h, l);
        const size_t o = (size_t)(n0 + ty + 8 * i) * 512 + k0 + tx;
        g_wqt_hi[o] = h; g_wqt_lo[o] = l;
    }
}

__global__ void knorm_split_kernel(const float* __restrict__ keys)
{
    const int warp = (blockIdx.x * blockDim.x + threadIdx.x) >> 5;
    const int lane = threadIdx.x & 31;
    if (warp >= NSn * NKn) return;
    const float* src = keys + (size_t)warp * KDn;
    float v0 = src[lane], v1 = src[lane + 32];
    float sq = v0 * v0 + v1 * v1;
#pragma unroll
    for (int o = 16; o > 0; o >>= 1) sq += __shfl_xor_sync(0xffffffffu, sq, o);
    const float scale = rsqrtf(sq);
    __nv_bfloat16 h, l;
    split_bf16(v0 * scale, h, l); g_khi[(size_t)warp * KDn + lane] = h;      g_klo[(size_t)warp * KDn + lane] = l;
    split_bf16(v1 * scale, h, l); g_khi[(size_t)warp * KDn + lane + 32] = h; g_klo[(size_t)warp * KDn + lane + 32] = l;
}

// ---------------------------------------------------------------------------
// gemm_q: double-buffered, LN epilogue (R14 proven config).
// ---------------------------------------------------------------------------
#define GST 65536
#define GSM_AH 0
#define GSM_AL 16384
#define GSM_BH 32768
#define GSM_BL 49152
#define GEMMQ_SMEM (2 * GST)

__global__ __launch_bounds__(256) void gemm_q_kernel(const float* __restrict__ bias,
                                                     const float* __restrict__ gamma,
                                                     const float* __restrict__ beta)
{
    extern __shared__ char smem[];
    const uint32_t sb = smem_u32(smem);
    const int tid  = threadIdx.x;
    const int lane = tid & 31;
    const int w    = tid >> 5;
    const int wm   = w & 3;
    const int wn   = w >> 2;
    const int m0   = blockIdx.y << 7;
    const int n0   = blockIdx.x << 7;
    const int K    = 512;

    float c[2][8][4];
#pragma unroll
    for (int mt = 0; mt < 2; ++mt)
#pragma unroll
        for (int nt = 0; nt < 8; ++nt)
#pragma unroll
            for (int j = 0; j < 4; ++j) c[mt][nt][j] = 0.f;

    const uint32_t a_off0 = (uint32_t)((wm * 32 + (lane & 15)) * 128 + ((lane >> 4) << 4));
    const uint32_t a_off1 = (uint32_t)((wm * 32 + 16 + (lane & 15)) * 128 + ((lane >> 4) << 4));
    const uint32_t b_row  = (uint32_t)(wn * 64 + (lane & 7) + ((lane >> 4) << 3));
    const uint32_t b_coff = (uint32_t)(((lane >> 3) & 1) << 4);

    auto load_tiles = [&](int stage, int ch) {
        const int k0 = ch << 6;
        const uint32_t stg = sb + stage * GST;
#pragma unroll
        for (int it = tid; it < 1024; it += 256) {
            const int r = it >> 3, p = it & 7;
            const uint32_t off = sw128((uint32_t)(r * 128 + p * 16));
            const size_t ga = (size_t)(m0 + r) * K + k0 + p * 8;
            cpa16(stg + GSM_AH + off, g_xhi + ga);
            cpa16(stg + GSM_AL + off, g_xlo + ga);
            const size_t gb = (size_t)(n0 + r) * K + k0 + p * 8;
            cpa16(stg + GSM_BH + off, g_wqt_hi + gb);
            cpa16(stg + GSM_BL + off, g_wqt_lo + gb);
        }
        cpa_commit();
    };

    load_tiles(0, 0);
    for (int ch = 0; ch < 8; ++ch) {
        if (ch + 1 < 8) { load_tiles((ch + 1) & 1, ch + 1); cpa_wait<1>(); }
        else            { cpa_wait<0>(); }
        __syncthreads();

        const uint32_t stg = sb + (ch & 1) * GST;
#pragma unroll
        for (int ks = 0; ks < 4; ++ks) {
            const uint32_t kof = (uint32_t)(ks * 32);
            uint32_t ah0[4], ah1[4], al0[4], al1[4];
            ldsm4(ah0[0], ah0[1], ah0[2], ah0[3], stg + GSM_AH + sw128(a_off0 + kof));
            ldsm4(ah1[0], ah1[1], ah1[2], ah1[3], stg + GSM_AH + sw128(a_off1 + kof));
            ldsm4(al0[0], al0[1], al0[2], al0[3], stg + GSM_AL + sw128(a_off0 + kof));
            ldsm4(al1[0], al1[1], al1[2], al1[3], stg + GSM_AL + sw128(a_off1 + kof));
#pragma unroll
            for (int p = 0; p < 4; ++p) {
                uint32_t bh[4], bl[4];
                const uint32_t boff = (uint32_t)((b_row + p * 16) * 128) + b_coff + kof;
                ldsm4(bh[0], bh[1], bh[2], bh[3], stg + GSM_BH + sw128(boff));
                ldsm4(bl[0], bl[1], bl[2], bl[3], stg + GSM_BL + sw128(boff));
                mma16816(c[0][2 * p],     ah0, bh);      mma16816(c[1][2 * p],     ah1, bh);
                mma16816(c[0][2 * p + 1], ah0, bh + 2);  mma16816(c[1][2 * p + 1], ah1, bh + 2);
                mma16816(c[0][2 * p],     ah0, bl);      mma16816(c[1][2 * p],     ah1, bl);
                mma16816(c[0][2 * p + 1], ah0, bl + 2);  mma16816(c[1][2 * p + 1], ah1, bl + 2);
                mma16816(c[0][2 * p],     al0, bh);      mma16816(c[1][2 * p],     al1, bh);
                mma16816(c[0][2 * p + 1], al0, bh + 2);  mma16816(c[1][2 * p + 1], al1, bh + 2);
            }
        }
        __syncthreads();
    }

#pragma unroll
    for (int mt = 0; mt < 2; ++mt) {
#pragma unroll
        for (int rh = 0; rh < 2; ++rh) {
            const int r = m0 + wm * 32 + mt * 16 + (lane >> 2) + rh * 8;
            float vals[16];
            float s = 0.f, s2 = 0.f;
#pragma unroll
            for (int nt = 0; nt < 8; ++nt)
#pragma unroll
                for (int jj = 0; jj < 2; ++jj) {
                    const int col = n0 + wn * 64 + nt * 8 + (lane & 3) * 2 + jj;
                    float v = c[mt][nt][rh * 2 + jj] + __ldg(bias + col);
                    vals[nt * 2 + jj] = v;
                    s += v; s2 += v * v;
                }
            s  += __shfl_xor_sync(0xffffffffu, s, 1);
            s  += __shfl_xor_sync(0xffffffffu, s, 2);
            s2 += __shfl_xor_sync(0xffffffffu, s2, 1);
            s2 += __shfl_xor_sync(0xffffffffu, s2, 2);
            const float mu  = s * (1.f / 64.f);
            const float var = s2 * (1.f / 64.f) - mu * mu;
            const float inv = rsqrtf(var + LN_EPS);
            const int slot = (n0 + wn * 64) >> 6;
#pragma unroll
            for (int nt = 0; nt < 8; ++nt) {
                const int kd = nt * 8 + (lane & 3) * 2;
                __nv_bfloat16 h0, l0, h1, l1;
                float o0 = (vals[nt * 2]     - mu) * inv * __ldg(gamma + kd)     + __ldg(beta + kd);
                float o1 = (vals[nt * 2 + 1] - mu) * inv * __ldg(gamma + kd + 1) + __ldg(beta + kd + 1);
                split_bf16(o0, h0, l0); split_bf16(o1, h1, l1);
                const size_t qi = ((size_t)r * NQn + slot) * KDn + kd;
                __nv_bfloat162 ph; ph.x = h0; ph.y = h1;
                __nv_bfloat162 pl; pl.x = l0; pl.y = l1;
                *(__nv_bfloat162*)(g_qhi + qi) = ph;
                *(__nv_bfloat162*)(g_qlo + qi) = pl;
            }
        }
    }
}

// ---------------------------------------------------------------------------
// attn_part (R12/R14 proven config)
// ---------------------------------------------------------------------------
#define ASM_QH 0
#define ASM_QL 8192
#define ASM_KH 16384
#define ASM_KL 24576
#define ASM_SC 32768
#define SC_PITCH 68
#define ATTN_SMEM (32768 + 64 * SC_PITCH * 4)

__global__ __launch_bounds__(256, 3) void attn_part_kernel()
{
    extern __shared__ char smem[];
    float* sc = (float*)(smem + ASM_SC);
    const uint32_t sb = smem_u32(smem);
    const int tid  = threadIdx.x;
    const int lane = tid & 31;
    const int w    = tid >> 5;
    const int wm   = w & 3;
    const int wn   = w >> 2;
    const int slot = blockIdx.y;
    const int t0   = blockIdx.x << 6;
    const int part = blockIdx.z;
    const int kbase = part << 9;

#pragma unroll
    for (int it = tid; it < 512; it += 256) {
        const int r = it >> 3, p = it & 7;
        const uint32_t off = sw128((uint32_t)(r * 128 + p * 16));
        const size_t g = ((size_t)(t0 + r) * NQn + slot) * KDn + p * 8;
        *(uint4*)(smem + ASM_QH + off) = *(const uint4*)(g_qhi + g);
        *(uint4*)(smem + ASM_QL + off) = *(const uint4*)(g_qlo + g);
    }

    const __nv_bfloat16* kbh = g_khi + ((size_t)(slot & 7) * NKn + kbase) * KDn;
    const __nv_bfloat16* kbl = g_klo + ((size_t)(slot & 7) * NKn + kbase) * KDn;

    const uint32_t a_off = (uint32_t)((wm * 16 + (lane & 15)) * 128 + ((lane >> 4) << 4));
    const uint32_t b_row = (uint32_t)(wn * 32 + (lane & 7) + ((lane >> 4) << 3));
    const uint32_t b_coff = (uint32_t)(((lane >> 3) & 1) << 4);

    int tv[8];
#pragma unroll
    for (int i = 0; i < 8; ++i) tv[i] = (int)0x80000000;

    for (int ch = 0; ch < 8; ++ch) {
#pragma unroll
        for (int it = tid; it < 512; it += 256) {
            const int r = it >> 3, p = it & 7;
            const uint32_t off = sw128((uint32_t)(r * 128 + p * 16));
            const size_t g = (size_t)(ch * 64 + r) * KDn + p * 8;
            *(uint4*)(smem + ASM_KH + off) = *(const uint4*)(kbh + g);
            *(uint4*)(smem + ASM_KL + off) = *(const uint4*)(kbl + g);
        }
        __syncthreads();

        float c[4][4];
#pragma unroll
        for (int nt = 0; nt < 4; ++nt)
#pragma unroll
            for (int j = 0; j < 4; ++j) c[nt][j] = 0.f;

#pragma unroll
        for (int ks = 0; ks < 4; ++ks) {
            const uint32_t kof = (uint32_t)(ks * 32);
            uint32_t ah[4], al[4];
            ldsm4(ah[0], ah[1], ah[2], ah[3], sb + ASM_QH + sw128(a_off + kof));
            ldsm4(al[0], al[1], al[2], al[3], sb + ASM_QL + sw128(a_off + kof));
#pragma unroll
            for (int p = 0; p < 2; ++p) {
                uint32_t bh[4], bl[4];
                const uint32_t boff = (uint32_t)((b_row + p * 16) * 128) + b_coff + kof;
                ldsm4(bh[0], bh[1], bh[2], bh[3], sb + ASM_KH + sw128(boff));
                ldsm4(bl[0], bl[1], bl[2], bl[3], sb + ASM_KL + sw128(boff));
                mma16816(c[2 * p],     ah, bh);
                mma16816(c[2 * p + 1], ah, bh + 2);
                mma16816(c[2 * p],     ah, bl);
                mma16816(c[2 * p + 1], ah, bl + 2);
                mma16816(c[2 * p],     al, bh);
                mma16816(c[2 * p + 1], al, bh + 2);
            }
        }

        {
            const int r = wm * 16 + (lane >> 2);
#pragma unroll
            for (int nt = 0; nt < 4; ++nt) {
                const int cb = wn * 32 + nt * 8 + (lane & 3) * 2;
                sc[r * SC_PITCH + cb]           = c[nt][0];
                sc[r * SC_PITCH + cb + 1]       = c[nt][1];
                sc[(r + 8) * SC_PITCH + cb]     = c[nt][2];
                sc[(r + 8) * SC_PITCH + cb + 1] = c[nt][3];
            }
        }
        __syncthreads();

        {
            const int t = tid >> 2, base = (tid & 3) * 16;
            const float4* rowp = (const float4*)(sc + t * SC_PITCH + base);
#pragma unroll
            for (int j4 = 0; j4 < 4; ++j4) {
                const float4 v = rowp[j4];
                const float m4 = fmaxf(fmaxf(v.x, v.y), fmaxf(v.z, v.w));
                if (packsc(m4, 0) > tv[7]) {
                    const int gi = kbase + ch * 64 + base + j4 * 4;
                    insp(packsc(v.x, gi),     tv);
                    insp(packsc(v.y, gi + 1), tv);
                    insp(packsc(v.z, gi + 2), tv);
                    insp(packsc(v.w, gi + 3), tv);
                }
            }
        }
    }

    {
        const int t = tid >> 2, sub = tid & 3;
        const size_t row = (size_t)(t0 + t) * NQn + slot;
        int* dv = g_topp + row * 128 + part * 32 + sub * 8;
#pragma unroll
        for (int i = 0; i < 8; ++i) dv[i] = tv[i];
    }
}

// ---------------------------------------------------------------------------
// Fused merge + softmax + V-gather (R14 proven)
// ---------------------------------------------------------------------------
__global__ __launch_bounds__(256) void attn_merge_gather(const float* __restrict__ values)
{
    __shared__ int   stg[64][33];
    __shared__ float spw[64][8];
    __shared__ int   spi[64][8];
    const int g = blockIdx.x * 256 + threadIdx.x;
    const int row = g >> 2;
    const int quarter = g & 3;
    const int lrow = threadIdx.x >> 2;
    if (row >= NROWS) return;

    {
        const int* src = g_topp + (size_t)row * 128 + quarter * 32;
        int ptr[4] = {0, 0, 0, 0};
        int out[8];
#pragma unroll
        for (int s = 0; s < 8; ++s) {
            int best = (int)0x80000000, br = 0;
#pragma unroll
            for (int run = 0; run < 4; ++run) {
                const int cv = (ptr[run] < 8) ? src[run * 8 + ptr[run]] : (int)0x80000000;
                if (cv > best) { best = cv; br = run; }
            }
            out[s] = best; ptr[br]++;
        }
#pragma unroll
        for (int i = 0; i < 8; ++i) stg[lrow][quarter * 8 + i] = out[i];
    }
    __syncthreads();

    if (quarter == 0) {
        int ptr[4] = {0, 0, 0, 0};
        int fin[8];
#pragma unroll
        for (int s = 0; s < 8; ++s) {
            int best = (int)0x80000000, br = 0;
#pragma unroll
            for (int run = 0; run < 4; ++run) {
                const int cv = (ptr[run] < 8) ? stg[lrow][run * 8 + ptr[run]] : (int)0x80000000;
                if (cv > best) { best = cv; br = run; }
            }
            fin[s] = best; ptr[br]++;
        }
        float sv[8];
#pragma unroll
        for (int i = 0; i < 8; ++i) {
            spi[lrow][i] = 2047 - (fin[i] & 2047);
            sv[i] = (float)(fin[i] >> 11) * (1.f / 32768.f);
        }
        const float mx = sv[0];
        float pr[8], denom = 0.f;
#pragma unroll
        for (int i = 0; i < 8; ++i) { pr[i] = expf(sv[i] - mx); denom += pr[i]; }
        const float inv = 1.f / denom;
#pragma unroll
        for (int i = 0; i < 8; ++i) spw[lrow][i] = pr[i] * inv;
    }
    __syncthreads();

    {
        const int d0 = quarter * 32;
        const int slot = row & 15;
        float pr[8]; int ir[8];
#pragma unroll
        for (int i = 0; i < 8; ++i) { pr[i] = spw[lrow][i]; ir[i] = spi[lrow][i]; }
        const float* vb = values + (size_t)(slot & 7) * NKn * VDn + d0;
        __nv_bfloat16* oh = g_atthi + (size_t)row * VDn + d0;
        __nv_bfloat16* ol = g_attlo + (size_t)row * VDn + d0;
#pragma unroll
        for (int dd = 0; dd < 32; dd += 4) {
            float4 acc = make_float4(0.f, 0.f, 0.f, 0.f);
#pragma unroll
            for (int i = 0; i < 8; ++i) {
                const float4 vv = *(const float4*)(vb + (size_t)ir[i] * VDn + dd);
                acc.x += pr[i] * vv.x; acc.y += pr[i] * vv.y;
                acc.z += pr[i] * vv.z; acc.w += pr[i] * vv.w;
            }
            __nv_bfloat16 h, l;
            split_bf16(acc.x, h, l); oh[dd]     = h; ol[dd]     = l;
            split_bf16(acc.y, h, l); oh[dd + 1] = h; ol[dd + 1] = l;
            split_bf16(acc.z, h, l); oh[dd + 2] = h; ol[dd + 2] = l;
            split_bf16(acc.w, h, l); oh[dd + 3] = h; ol[dd + 3] = l;
        }
    }
}

// ---------------------------------------------------------------------------
// gemm_out: 128x256 block tiles (2 N-tiles), double-buffered cp.async.
// 8 warps as 2m x 4n, warp tile 64x64. K = 192 (3 chunks of 64).
// Stage: A 32KB + B 64KB = 96KB; 2 stages = 192KB; 1 CTA/SM (reg-limited).
// ---------------------------------------------------------------------------
#define OST 98304
#define OSM_AH 0
#define OSM_AL 16384
#define OSM_BH 32768
#define OSM_BL 65536
#define GEMMO_SMEM (2 * OST)

__global__ __launch_bounds__(256) void gemm_out_kernel(float* __restrict__ C)
{
    extern __shared__ char smem[];
    const uint32_t sb = smem_u32(smem);
    const int tid  = threadIdx.x;
    const int lane = tid & 31;
    const int w    = tid >> 5;
    const int wm   = w & 1;          // 2 m-warps (64 rows each)
    const int wn   = w >> 1;         // 4 n-warps (64 cols each)
    const int m0   = blockIdx.y << 7;
    const int n0   = blockIdx.x << 8;

    float c[4][8][4];
#pragma unroll
    for (int mt = 0; mt < 4; ++mt)
#pragma unroll
        for (int nt = 0; nt < 8; ++nt)
#pragma unroll
            for (int j = 0; j < 4; ++j) c[mt][nt][j] = 0.f;

    const uint32_t a_base = (uint32_t)((wm * 64 + (lane & 15)) * 128 + ((lane >> 4) << 4));
    const uint32_t b_row  = (uint32_t)(wn * 64 + (lane & 7) + ((lane >> 4) << 3));
    const uint32_t b_coff = (uint32_t)(((lane >> 3) & 1) << 4);

    auto load_tiles = [&](int stage, int ch) {
        const uint32_t stg = sb + stage * OST;
        // A: 128 rows x 64 k (hi+lo)
#pragma unroll
        for (int it = tid; it < 1024; it += 256) {
            const int r = it >> 3, p = it & 7;
            const uint32_t off = sw128((uint32_t)(r * 128 + p * 16));
            if (ch < 2) {
                const size_t ga = (size_t)(m0 + r) * VDn + (ch << 6) + p * 8;
                cpa16(stg + OSM_AH + off, g_atthi + ga);
                cpa16(stg + OSM_AL + off, g_attlo + ga);
            } else {
                const size_t ga = (size_t)(m0 + r) * KDn + p * 8;
                cpa16(stg + OSM_AH + off, g_qhi + ga);
                cpa16(stg + OSM_AL + off, g_qlo + ga);
            }
        }
        // B: 256 n-rows x 64 k (hi+lo)
#pragma unroll
        for (int it = tid; it < 2048; it += 256) {
            const int r = it >> 3, p = it & 7;
            const uint32_t off = sw128((uint32_t)(r * 128 + p * 16));
            if (ch < 2) {
                const size_t gb = (size_t)(n0 + r) * VDn + (ch << 6) + p * 8;
                cpa16(stg + OSM_BH + off, g_wmemt_hi + gb);
                cpa16(stg + OSM_BL + off, g_wmemt_lo + gb);
            } else {
                const size_t gb = (size_t)(n0 + r) * KDn + p * 8;
                cpa16(stg + OSM_BH + off, g_wrmt_hi + gb);
                cpa16(stg + OSM_BL + off, g_wrmt_lo + gb);
            }
        }
        cpa_commit();
    };

    load_tiles(0, 0);
    for (int ch = 0; ch < 3; ++ch) {
        if (ch + 1 < 3) { load_tiles((ch + 1) & 1, ch + 1); cpa_wait<1>(); }
        else            { cpa_wait<0>(); }
        __syncthreads();

        const uint32_t stg = sb + (ch & 1) * OST;
#pragma unroll
        for (int ks = 0; ks < 4; ++ks) {
            const uint32_t kof = (uint32_t)(ks * 32);
            uint32_t ah[4][4], al[4][4];
#pragma unroll
            for (int mt = 0; mt < 4; ++mt) {
                const uint32_t ao = a_base + (uint32_t)(mt * 16 * 128) + kof;
                ldsm4(ah[mt][0], ah[mt][1], ah[mt][2], ah[mt][3], stg + OSM_AH + sw128(ao));
                ldsm4(al[mt][0], al[mt][1], al[mt][2], al[mt][3], stg + OSM_AL + sw128(ao));
            }
#pragma unroll
            for (int p = 0; p < 4; ++p) {
                uint32_t bh[4], bl[4];
                const uint32_t boff = (uint32_t)((b_row + p * 16) * 128) + b_coff + kof;
                ldsm4(bh[0], bh[1], bh[2], bh[3], stg + OSM_BH + sw128(boff));
                ldsm4(bl[0], bl[1], bl[2], bl[3], stg + OSM_BL + sw128(boff));
#pragma unroll
                for (int mt = 0; mt < 4; ++mt) {
                    mma16816(c[mt][2 * p],     ah[mt], bh);
                    mma16816(c[mt][2 * p + 1], ah[mt], bh + 2);
                    mma16816(c[mt][2 * p],     ah[mt], bl);
                    mma16816(c[mt][2 * p + 1], ah[mt], bl + 2);
                    mma16816(c[mt][2 * p],     al[mt], bh);
                    mma16816(c[mt][2 * p + 1], al[mt], bh + 2);
                }
            }
        }
        __syncthreads();
    }

#pragma unroll
    for (int mt = 0; mt < 4; ++mt) {
#pragma unroll
        for (int nt = 0; nt < 8; ++nt) {
#pragma unroll
            for (int j = 0; j < 4; ++j) {
                const int r   = m0 + wm * 64 + mt * 16 + (lane >> 2) + (j >= 2 ? 8 : 0);
                const int col = n0 + wn * 64 + nt * 8 + (lane & 3) * 2 + (j & 1);
                const float v = c[mt][nt][j] + g_brm[col];
                const int token = r >> 4;
                const int slot  = r & 15;
                const size_t base = (slot < NSn) ? 0 : (size_t)BS_TOK * NSn * MEMn;
                C[base + (size_t)(token * NSn + (slot & 7)) * MEMn + col] = v;
            }
        }
    }
}

// ---------------------------------------------------------------------------
// Host launcher.
// ---------------------------------------------------------------------------
extern "C" void kernel_launch(void* const* d_in, const int* in_sizes, int n_in,
                              void* d_out, int out_size)
{
    const float* x      = (const float*)d_in[0];
    const float* Wq     = (const float*)d_in[1];
    const float* bq     = (const float*)d_in[2];
    const float* ln_g   = (const float*)d_in[3];
    const float* ln_b   = (const float*)d_in[4];
    const float* keys   = (const float*)d_in[5];
    const float* values = (const float*)d_in[6];
    const float* Wres   = (const float*)d_in[7];
    const float* bres   = (const float*)d_in[8];
    const float* Wmem   = (const float*)d_in[9];
    const float* bmem   = (const float*)d_in[10];
    float* out = (float*)d_out;

    cudaFuncSetAttribute(gemm_q_kernel,    cudaFuncAttributeMaxDynamicSharedMemorySize, GEMMQ_SMEM);
    cudaFuncSetAttribute(gemm_out_kernel,  cudaFuncAttributeMaxDynamicSharedMemorySize, GEMMO_SMEM);
    cudaFuncSetAttribute(attn_part_kernel, cudaFuncAttributeMaxDynamicSharedMemorySize, ATTN_SMEM);

    prep_weights<<<4482, 256>>>(x, Wres, Wmem, bres, bmem);
    tsplit_wq_kernel<<<dim3(32, 16), 256>>>(Wq);
    knorm_split_kernel<<<2048, 256>>>(keys);
    gemm_q_kernel<<<dim3(8, 16), 256, GEMMQ_SMEM>>>(bq, ln_g, ln_b);   // profiled
    attn_part_kernel<<<dim3(32, 16, 4), 256, ATTN_SMEM>>>();
    attn_merge_gather<<<512, 256>>>(values);
    gemm_out_kernel<<<dim3(2, 256), 256, GEMMO_SMEM>>>(out);
}

// round 16
// speedup vs baseline: 1.1316x; 1.0077x over previous
#include <cuda_runtime.h>
#include <cuda_bf16.h>
#include <math.h>
#include <float.h>
#include <stdint.h>

#define BS_TOK 2048
#define NQn 16
#define NSn 8
#define KDn 64
#define NKn 2048
#define VDn 128
#define MEMn 512
#define LN_EPS 1e-5f
#define NROWS (BS_TOK * NQn)

// ---------------------------------------------------------------------------
// Scratch globals
// ---------------------------------------------------------------------------
__device__ __nv_bfloat16 g_xhi[BS_TOK * 512],        g_xlo[BS_TOK * 512];
__device__ __nv_bfloat16 g_wqt_hi[1024 * 512],       g_wqt_lo[1024 * 512];
__device__ __nv_bfloat16 g_qhi[NROWS * KDn],         g_qlo[NROWS * KDn];
__device__ __nv_bfloat16 g_khi[NSn * NKn * KDn],     g_klo[NSn * NKn * KDn];
__device__ __nv_bfloat16 g_wmemt_hi[MEMn * VDn],     g_wmemt_lo[MEMn * VDn];
__device__ __nv_bfloat16 g_wrmt_hi[MEMn * KDn],      g_wrmt_lo[MEMn * KDn];
__device__ float         g_brm[MEMn];
__device__ __nv_bfloat16 g_atthi[NROWS * VDn],       g_attlo[NROWS * VDn];
__device__ int g_topp[(size_t)NROWS * 128];

// ---------------------------------------------------------------------------
// Helpers
// ---------------------------------------------------------------------------
__device__ __forceinline__ uint32_t smem_u32(const void* p) {
    uint32_t a;
    asm("{ .reg .u64 t; cvta.to.shared.u64 t, %1; cvt.u32.u64 %0, t; }" : "=r"(a) : "l"(p));
    return a;
}
__device__ __forceinline__ uint32_t sw128(uint32_t off) { return off ^ ((off >> 3) & 0x70); }

__device__ __forceinline__ void mma16816(float c[4], const uint32_t a[4], const uint32_t b[2])
{
    asm("mma.sync.aligned.m16n8k16.row.col.f32.bf16.bf16.f32 "
        "{%0,%1,%2,%3},{%4,%5,%6,%7},{%8,%9},{%0,%1,%2,%3};"
        : "+f"(c[0]), "+f"(c[1]), "+f"(c[2]), "+f"(c[3])
        : "r"(a[0]), "r"(a[1]), "r"(a[2]), "r"(a[3]), "r"(b[0]), "r"(b[1]));
}
__device__ __forceinline__ void ldsm4(uint32_t& r0, uint32_t& r1, uint32_t& r2, uint32_t& r3, uint32_t addr)
{
    asm volatile("ldmatrix.sync.aligned.m8n8.x4.shared.b16 {%0,%1,%2,%3}, [%4];"
                 : "=r"(r0), "=r"(r1), "=r"(r2), "=r"(r3) : "r"(addr));
}
__device__ __forceinline__ void cpa16(uint32_t s, const void* g) {
    asm volatile("cp.async.cg.shared.global [%0], [%1], 16;" :: "r"(s), "l"(g));
}
__device__ __forceinline__ void cpa_commit() { asm volatile("cp.async.commit_group;" ::: "memory"); }
template<int N> __device__ __forceinline__ void cpa_wait() {
    asm volatile("cp.async.wait_group %0;" :: "n"(N) : "memory");
}
__device__ __forceinline__ void split_bf16(float v, __nv_bfloat16& h, __nv_bfloat16& l) {
    h = __float2bfloat16(v);
    l = __float2bfloat16(v - __bfloat162float(h));
}
__device__ __forceinline__ int packsc(float s, int idx) {
    const int q = __float2int_rn(s * 32768.f);
    return (q << 11) | (2047 - idx);
}
__device__ __forceinline__ void insp(int s, int tv[8]) {
#pragma unroll
    for (int i = 0; i < 8; ++i) {
        const int lo = min(tv[i], s);
        tv[i] = max(tv[i], s);
        s = lo;
    }
}

// ---------------------------------------------------------------------------
// Unified prep: x split | Wmem/Wrm/brm | Wq tiled transpose | key norm
// Grid: [0,4096) x | [4096,4352) Wmem | [4352,4480) Wrm | [4480,4482) brm |
//       [4482,4994) Wq-transpose tiles | [4994,7042) key rows
// ---------------------------------------------------------------------------
__global__ void prep_all(const float* __restrict__ x,
                         const float* __restrict__ Wq,
                         const float* __restrict__ keys,
                         const float* __restrict__ Wres, const float* __restrict__ Wmem,
                         const float* __restrict__ bres, const float* __restrict__ bmem)
{
    __shared__ float tile[32][33];
    const int b = blockIdx.x;
    const int tid = threadIdx.x;
    __nv_bfloat16 h, l;
    if (b < 4096) {
        const int i = b * 256 + tid;
        split_bf16(x[i], h, l);
        g_xhi[i] = h; g_xlo[i] = l;
    } else if (b < 4352) {
        const int i = (b - 4096) * 256 + tid;
        const int k = i >> 9, n = i & 511;
        split_bf16(Wmem[i], h, l);
        g_wmemt_hi[(size_t)n * 128 + k] = h;
        g_wmemt_lo[(size_t)n * 128 + k] = l;
    } else if (b < 4480) {
        const int i = (b - 4352) * 256 + tid;
        const int m = i >> 9, n = i & 511;
        float acc = 0.f;
#pragma unroll 8
        for (int k = 0; k < VDn; ++k)
            acc += Wres[m * VDn + k] * Wmem[k * MEMn + n];
        split_bf16(acc, h, l);
        g_wrmt_hi[(size_t)n * KDn + m] = h;
        g_wrmt_lo[(size_t)n * KDn + m] = l;
    } else if (b < 4482) {
        const int n = (b - 4480) * 256 + tid;
        float acc = bmem[n];
#pragma unroll 8
        for (int k = 0; k < VDn; ++k)
            acc += bres[k] * Wmem[k * MEMn + n];
        g_brm[n] = acc;
    } else if (b < 4994) {
        // Wq transpose-split: 32x32 tile
        const int t  = b - 4482;
        const int n0 = (t & 31) << 5;
        const int k0 = (t >> 5) << 5;
        const int tx = tid & 31;
        const int ty = tid >> 5;
#pragma unroll
        for (int i = 0; i < 4; ++i)
            tile[ty + 8 * i][tx] = Wq[(size_t)(k0 + ty + 8 * i) * 1024 + n0 + tx];
        __syncthreads();
#pragma unroll
        for (int i = 0; i < 4; ++i) {
            split_bf16(tile[tx][ty + 8 * i], h, l);
            const size_t o = (size_t)(n0 + ty + 8 * i) * 512 + k0 + tx;
            g_wqt_hi[o] = h; g_wqt_lo[o] = l;
        }
    } else {
        // key L2-normalize + split: one warp per key row
        const int warp = (b - 4994) * 8 + (tid >> 5);
        const int lane = tid & 31;
        const float* src = keys + (size_t)warp * KDn;
        float v0 = src[lane], v1 = src[lane + 32];
        float sq = v0 * v0 + v1 * v1;
#pragma unroll
        for (int o = 16; o > 0; o >>= 1) sq += __shfl_xor_sync(0xffffffffu, sq, o);
        const float scale = rsqrtf(sq);
        split_bf16(v0 * scale, h, l); g_khi[(size_t)warp * KDn + lane] = h;      g_klo[(size_t)warp * KDn + lane] = l;
        split_bf16(v1 * scale, h, l); g_khi[(size_t)warp * KDn + lane + 32] = h; g_klo[(size_t)warp * KDn + lane + 32] = l;
    }
}

// ---------------------------------------------------------------------------
// gemm_q: double-buffered, LN epilogue (R14 proven config).
// ---------------------------------------------------------------------------
#define GST 65536
#define GSM_AH 0
#define GSM_AL 16384
#define GSM_BH 32768
#define GSM_BL 49152
#define GEMMQ_SMEM (2 * GST)

__global__ __launch_bounds__(256) void gemm_q_kernel(const float* __restrict__ bias,
                                                     const float* __restrict__ gamma,
                                                     const float* __restrict__ beta)
{
    extern __shared__ char smem[];
    const uint32_t sb = smem_u32(smem);
    const int tid  = threadIdx.x;
    const int lane = tid & 31;
    const int w    = tid >> 5;
    const int wm   = w & 3;
    const int wn   = w >> 2;
    const int m0   = blockIdx.y << 7;
    const int n0   = blockIdx.x << 7;
    const int K    = 512;

    float c[2][8][4];
#pragma unroll
    for (int mt = 0; mt < 2; ++mt)
#pragma unroll
        for (int nt = 0; nt < 8; ++nt)
#pragma unroll
            for (int j = 0; j < 4; ++j) c[mt][nt][j] = 0.f;

    const uint32_t a_off0 = (uint32_t)((wm * 32 + (lane & 15)) * 128 + ((lane >> 4) << 4));
    const uint32_t a_off1 = (uint32_t)((wm * 32 + 16 + (lane & 15)) * 128 + ((lane >> 4) << 4));
    const uint32_t b_row  = (uint32_t)(wn * 64 + (lane & 7) + ((lane >> 4) << 3));
    const uint32_t b_coff = (uint32_t)(((lane >> 3) & 1) << 4);

    auto load_tiles = [&](int stage, int ch) {
        const int k0 = ch << 6;
        const uint32_t stg = sb + stage * GST;
#pragma unroll
        for (int it = tid; it < 1024; it += 256) {
            const int r = it >> 3, p = it & 7;
            const uint32_t off = sw128((uint32_t)(r * 128 + p * 16));
            const size_t ga = (size_t)(m0 + r) * K + k0 + p * 8;
            cpa16(stg + GSM_AH + off, g_xhi + ga);
            cpa16(stg + GSM_AL + off, g_xlo + ga);
            const size_t gb = (size_t)(n0 + r) * K + k0 + p * 8;
            cpa16(stg + GSM_BH + off, g_wqt_hi + gb);
            cpa16(stg + GSM_BL + off, g_wqt_lo + gb);
        }
        cpa_commit();
    };

    load_tiles(0, 0);
    for (int ch = 0; ch < 8; ++ch) {
        if (ch + 1 < 8) { load_tiles((ch + 1) & 1, ch + 1); cpa_wait<1>(); }
        else            { cpa_wait<0>(); }
        __syncthreads();

        const uint32_t stg = sb + (ch & 1) * GST;
#pragma unroll
        for (int ks = 0; ks < 4; ++ks) {
            const uint32_t kof = (uint32_t)(ks * 32);
            uint32_t ah0[4], ah1[4], al0[4], al1[4];
            ldsm4(ah0[0], ah0[1], ah0[2], ah0[3], stg + GSM_AH + sw128(a_off0 + kof));
            ldsm4(ah1[0], ah1[1], ah1[2], ah1[3], stg + GSM_AH + sw128(a_off1 + kof));
            ldsm4(al0[0], al0[1], al0[2], al0[3], stg + GSM_AL + sw128(a_off0 + kof));
            ldsm4(al1[0], al1[1], al1[2], al1[3], stg + GSM_AL + sw128(a_off1 + kof));
#pragma unroll
            for (int p = 0; p < 4; ++p) {
                uint32_t bh[4], bl[4];
                const uint32_t boff = (uint32_t)((b_row + p * 16) * 128) + b_coff + kof;
                ldsm4(bh[0], bh[1], bh[2], bh[3], stg + GSM_BH + sw128(boff));
                ldsm4(bl[0], bl[1], bl[2], bl[3], stg + GSM_BL + sw128(boff));
                mma16816(c[0][2 * p],     ah0, bh);      mma16816(c[1][2 * p],     ah1, bh);
                mma16816(c[0][2 * p + 1], ah0, bh + 2);  mma16816(c[1][2 * p + 1], ah1, bh + 2);
                mma16816(c[0][2 * p],     ah0, bl);      mma16816(c[1][2 * p],     ah1, bl);
                mma16816(c[0][2 * p + 1], ah0, bl + 2);  mma16816(c[1][2 * p + 1], ah1, bl + 2);
                mma16816(c[0][2 * p],     al0, bh);      mma16816(c[1][2 * p],     al1, bh);
                mma16816(c[0][2 * p + 1], al0, bh + 2);  mma16816(c[1][2 * p + 1], al1, bh + 2);
            }
        }
        __syncthreads();
    }

#pragma unroll
    for (int mt = 0; mt < 2; ++mt) {
#pragma unroll
        for (int rh = 0; rh < 2; ++rh) {
            const int r = m0 + wm * 32 + mt * 16 + (lane >> 2) + rh * 8;
            float vals[16];
            float s = 0.f, s2 = 0.f;
#pragma unroll
            for (int nt = 0; nt < 8; ++nt)
#pragma unroll
                for (int jj = 0; jj < 2; ++jj) {
                    const int col = n0 + wn * 64 + nt * 8 + (lane & 3) * 2 + jj;
                    float v = c[mt][nt][rh * 2 + jj] + __ldg(bias + col);
                    vals[nt * 2 + jj] = v;
                    s += v; s2 += v * v;
                }
            s  += __shfl_xor_sync(0xffffffffu, s, 1);
            s  += __shfl_xor_sync(0xffffffffu, s, 2);
            s2 += __shfl_xor_sync(0xffffffffu, s2, 1);
            s2 += __shfl_xor_sync(0xffffffffu, s2, 2);
            const float mu  = s * (1.f / 64.f);
            const float var = s2 * (1.f / 64.f) - mu * mu;
            const float inv = rsqrtf(var + LN_EPS);
            const int slot = (n0 + wn * 64) >> 6;
#pragma unroll
            for (int nt = 0; nt < 8; ++nt) {
                const int kd = nt * 8 + (lane & 3) * 2;
                __nv_bfloat16 h0, l0, h1, l1;
                float o0 = (vals[nt * 2]     - mu) * inv * __ldg(gamma + kd)     + __ldg(beta + kd);
                float o1 = (vals[nt * 2 + 1] - mu) * inv * __ldg(gamma + kd + 1) + __ldg(beta + kd + 1);
                split_bf16(o0, h0, l0); split_bf16(o1, h1, l1);
                const size_t qi = ((size_t)r * NQn + slot) * KDn + kd;
                __nv_bfloat162 ph; ph.x = h0; ph.y = h1;
                __nv_bfloat162 pl; pl.x = l0; pl.y = l1;
                *(__nv_bfloat162*)(g_qhi + qi) = ph;
                *(__nv_bfloat162*)(g_qlo + qi) = pl;
            }
        }
    }
}

// ---------------------------------------------------------------------------
// attn_part (R12/R14 proven config)
// ---------------------------------------------------------------------------
#define ASM_QH 0
#define ASM_QL 8192
#define ASM_KH 16384
#define ASM_KL 24576
#define ASM_SC 32768
#define SC_PITCH 68
#define ATTN_SMEM (32768 + 64 * SC_PITCH * 4)

__global__ __launch_bounds__(256, 3) void attn_part_kernel()
{
    extern __shared__ char smem[];
    float* sc = (float*)(smem + ASM_SC);
    const uint32_t sb = smem_u32(smem);
    const int tid  = threadIdx.x;
    const int lane = tid & 31;
    const int w    = tid >> 5;
    const int wm   = w & 3;
    const int wn   = w >> 2;
    const int slot = blockIdx.y;
    const int t0   = blockIdx.x << 6;
    const int part = blockIdx.z;
    const int kbase = part << 9;

#pragma unroll
    for (int it = tid; it < 512; it += 256) {
        const int r = it >> 3, p = it & 7;
        const uint32_t off = sw128((uint32_t)(r * 128 + p * 16));
        const size_t g = ((size_t)(t0 + r) * NQn + slot) * KDn + p * 8;
        *(uint4*)(smem + ASM_QH + off) = *(const uint4*)(g_qhi + g);
        *(uint4*)(smem + ASM_QL + off) = *(const uint4*)(g_qlo + g);
    }

    const __nv_bfloat16* kbh = g_khi + ((size_t)(slot & 7) * NKn + kbase) * KDn;
    const __nv_bfloat16* kbl = g_klo + ((size_t)(slot & 7) * NKn + kbase) * KDn;

    const uint32_t a_off = (uint32_t)((wm * 16 + (lane & 15)) * 128 + ((lane >> 4) << 4));
    const uint32_t b_row = (uint32_t)(wn * 32 + (lane & 7) + ((lane >> 4) << 3));
    const uint32_t b_coff = (uint32_t)(((lane >> 3) & 1) << 4);

    int tv[8];
#pragma unroll
    for (int i = 0; i < 8; ++i) tv[i] = (int)0x80000000;

    for (int ch = 0; ch < 8; ++ch) {
#pragma unroll
        for (int it = tid; it < 512; it += 256) {
            const int r = it >> 3, p = it & 7;
            const uint32_t off = sw128((uint32_t)(r * 128 + p * 16));
            const size_t g = (size_t)(ch * 64 + r) * KDn + p * 8;
            *(uint4*)(smem + ASM_KH + off) = *(const uint4*)(kbh + g);
            *(uint4*)(smem + ASM_KL + off) = *(const uint4*)(kbl + g);
        }
        __syncthreads();

        float c[4][4];
#pragma unroll
        for (int nt = 0; nt < 4; ++nt)
#pragma unroll
            for (int j = 0; j < 4; ++j) c[nt][j] = 0.f;

#pragma unroll
        for (int ks = 0; ks < 4; ++ks) {
            const uint32_t kof = (uint32_t)(ks * 32);
            uint32_t ah[4], al[4];
            ldsm4(ah[0], ah[1], ah[2], ah[3], sb + ASM_QH + sw128(a_off + kof));
            ldsm4(al[0], al[1], al[2], al[3], sb + ASM_QL + sw128(a_off + kof));
#pragma unroll
            for (int p = 0; p < 2; ++p) {
                uint32_t bh[4], bl[4];
                const uint32_t boff = (uint32_t)((b_row + p * 16) * 128) + b_coff + kof;
                ldsm4(bh[0], bh[1], bh[2], bh[3], sb + ASM_KH + sw128(boff));
                ldsm4(bl[0], bl[1], bl[2], bl[3], sb + ASM_KL + sw128(boff));
                mma16816(c[2 * p],     ah, bh);
                mma16816(c[2 * p + 1], ah, bh + 2);
                mma16816(c[2 * p],     ah, bl);
                mma16816(c[2 * p + 1], ah, bl + 2);
                mma16816(c[2 * p],     al, bh);
                mma16816(c[2 * p + 1], al, bh + 2);
            }
        }

        {
            const int r = wm * 16 + (lane >> 2);
#pragma unroll
            for (int nt = 0; nt < 4; ++nt) {
                const int cb = wn * 32 + nt * 8 + (lane & 3) * 2;
                sc[r * SC_PITCH + cb]           = c[nt][0];
                sc[r * SC_PITCH + cb + 1]       = c[nt][1];
                sc[(r + 8) * SC_PITCH + cb]     = c[nt][2];
                sc[(r + 8) * SC_PITCH + cb + 1] = c[nt][3];
            }
        }
        __syncthreads();

        {
            const int t = tid >> 2, base = (tid & 3) * 16;
            const float4* rowp = (const float4*)(sc + t * SC_PITCH + base);
#pragma unroll
            for (int j4 = 0; j4 < 4; ++j4) {
                const float4 v = rowp[j4];
                const float m4 = fmaxf(fmaxf(v.x, v.y), fmaxf(v.z, v.w));
                if (packsc(m4, 0) > tv[7]) {
                    const int gi = kbase + ch * 64 + base + j4 * 4;
                    insp(packsc(v.x, gi),     tv);
                    insp(packsc(v.y, gi + 1), tv);
                    insp(packsc(v.z, gi + 2), tv);
                    insp(packsc(v.w, gi + 3), tv);
                }
            }
        }
    }

    {
        const int t = tid >> 2, sub = tid & 3;
        const size_t row = (size_t)(t0 + t) * NQn + slot;
        int* dv = g_topp + row * 128 + part * 32 + sub * 8;
#pragma unroll
        for (int i = 0; i < 8; ++i) dv[i] = tv[i];
    }
}

// ---------------------------------------------------------------------------
// Fused merge + softmax + V-gather, vectorized candidate loads.
// 4 threads/row, 64 rows/block.  (profiled launch this round)
// ---------------------------------------------------------------------------
__global__ __launch_bounds__(256) void attn_merge_gather(const float* __restrict__ values)
{
    __shared__ int   stg[64][33];
    __shared__ float spw[64][8];
    __shared__ int   spi[64][8];
    const int g = blockIdx.x * 256 + threadIdx.x;
    const int row = g >> 2;
    const int quarter = g & 3;
    const int lrow = threadIdx.x >> 2;
    if (row >= NROWS) return;

    // Stage 1: vector-load 4 sorted runs of 8 into registers, merge -> top-8
    {
        const int4* src = (const int4*)(g_topp + (size_t)row * 128 + quarter * 32);
        int rn[4][8];
#pragma unroll
        for (int rr = 0; rr < 4; ++rr) {
            const int4 a = src[rr * 2];
            const int4 b = src[rr * 2 + 1];
            rn[rr][0] = a.x; rn[rr][1] = a.y; rn[rr][2] = a.z; rn[rr][3] = a.w;
            rn[rr][4] = b.x; rn[rr][5] = b.y; rn[rr][6] = b.z; rn[rr][7] = b.w;
        }
        int ptr[4] = {0, 0, 0, 0};
        int out[8];
#pragma unroll
        for (int s = 0; s < 8; ++s) {
            int best = (int)0x80000000, br = 0;
#pragma unroll
            for (int run = 0; run < 4; ++run) {
                const int cv = (ptr[run] < 8) ? rn[run][ptr[run] & 7] : (int)0x80000000;
                if (cv > best) { best = cv; br = run; }
            }
            out[s] = best; ptr[br]++;
        }
#pragma unroll
        for (int i = 0; i < 8; ++i) stg[lrow][quarter * 8 + i] = out[i];
    }
    __syncthreads();

    if (quarter == 0) {
        int ptr[4] = {0, 0, 0, 0};
        int fin[8];
#pragma unroll
        for (int s = 0; s < 8; ++s) {
            int best = (int)0x80000000, br = 0;
#pragma unroll
            for (int run = 0; run < 4; ++run) {
                const int cv = (ptr[run] < 8) ? stg[lrow][run * 8 + ptr[run]] : (int)0x80000000;
                if (cv > best) { best = cv; br = run; }
            }
            fin[s] = best; ptr[br]++;
        }
        float sv[8];
#pragma unroll
        for (int i = 0; i < 8; ++i) {
            spi[lrow][i] = 2047 - (fin[i] & 2047);
            sv[i] = (float)(fin[i] >> 11) * (1.f / 32768.f);
        }
        const float mx = sv[0];
        float pr[8], denom = 0.f;
#pragma unroll
        for (int i = 0; i < 8; ++i) { pr[i] = expf(sv[i] - mx); denom += pr[i]; }
        const float inv = 1.f / denom;
#pragma unroll
        for (int i = 0; i < 8; ++i) spw[lrow][i] = pr[i] * inv;
    }
    __syncthreads();

    {
        const int d0 = quarter * 32;
        const int slot = row & 15;
        float pr[8]; int ir[8];
#pragma unroll
        for (int i = 0; i < 8; ++i) { pr[i] = spw[lrow][i]; ir[i] = spi[lrow][i]; }
        const float* vb = values + (size_t)(slot & 7) * NKn * VDn + d0;
        __nv_bfloat16* oh = g_atthi + (size_t)row * VDn + d0;
        __nv_bfloat16* ol = g_attlo + (size_t)row * VDn + d0;
#pragma unroll
        for (int dd = 0; dd < 32; dd += 4) {
            float4 acc = make_float4(0.f, 0.f, 0.f, 0.f);
#pragma unroll
            for (int i = 0; i < 8; ++i) {
                const float4 vv = *(const float4*)(vb + (size_t)ir[i] * VDn + dd);
                acc.x += pr[i] * vv.x; acc.y += pr[i] * vv.y;
                acc.z += pr[i] * vv.z; acc.w += pr[i] * vv.w;
            }
            __nv_bfloat16 h, l;
            split_bf16(acc.x, h, l); oh[dd]     = h; ol[dd]     = l;
            split_bf16(acc.y, h, l); oh[dd + 1] = h; ol[dd + 1] = l;
            split_bf16(acc.z, h, l); oh[dd + 2] = h; ol[dd + 2] = l;
            split_bf16(acc.w, h, l); oh[dd + 3] = h; ol[dd + 3] = l;
        }
    }
}

// ---------------------------------------------------------------------------
// gemm_out: 128x256 tiles, double-buffered (R15 proven config).
// ---------------------------------------------------------------------------
#define OST 98304
#define OSM_AH 0
#define OSM_AL 16384
#define OSM_BH 32768
#define OSM_BL 65536
#define GEMMO_SMEM (2 * OST)

__global__ __launch_bounds__(256) void gemm_out_kernel(float* __restrict__ C)
{
    extern __shared__ char smem[];
    const uint32_t sb = smem_u32(smem);
    const int tid  = threadIdx.x;
    const int lane = tid & 31;
    const int w    = tid >> 5;
    const int wm   = w & 1;
    const int wn   = w >> 1;
    const int m0   = blockIdx.y << 7;
    const int n0   = blockIdx.x << 8;

    float c[4][8][4];
#pragma unroll
    for (int mt = 0; mt < 4; ++mt)
#pragma unroll
        for (int nt = 0; nt < 8; ++nt)
#pragma unroll
            for (int j = 0; j < 4; ++j) c[mt][nt][j] = 0.f;

    const uint32_t a_base = (uint32_t)((wm * 64 + (lane & 15)) * 128 + ((lane >> 4) << 4));
    const uint32_t b_row  = (uint32_t)(wn * 64 + (lane & 7) + ((lane >> 4) << 3));
    const uint32_t b_coff = (uint32_t)(((lane >> 3) & 1) << 4);

    auto load_tiles = [&](int stage, int ch) {
        const uint32_t stg = sb + stage * OST;
#pragma unroll
        for (int it = tid; it < 1024; it += 256) {
            const int r = it >> 3, p = it & 7;
            const uint32_t off = sw128((uint32_t)(r * 128 + p * 16));
            if (ch < 2) {
                const size_t ga = (size_t)(m0 + r) * VDn + (ch << 6) + p * 8;
                cpa16(stg + OSM_AH + off, g_atthi + ga);
                cpa16(stg + OSM_AL + off, g_attlo + ga);
            } else {
                const size_t ga = (size_t)(m0 + r) * KDn + p * 8;
                cpa16(stg + OSM_AH + off, g_qhi + ga);
                cpa16(stg + OSM_AL + off, g_qlo + ga);
            }
        }
#pragma unroll
        for (int it = tid; it < 2048; it += 256) {
            const int r = it >> 3, p = it & 7;
            const uint32_t off = sw128((uint32_t)(r * 128 + p * 16));
            if (ch < 2) {
                const size_t gb = (size_t)(n0 + r) * VDn + (ch << 6) + p * 8;
                cpa16(stg + OSM_BH + off, g_wmemt_hi + gb);
                cpa16(stg + OSM_BL + off, g_wmemt_lo + gb);
            } else {
                const size_t gb = (size_t)(n0 + r) * KDn + p * 8;
                cpa16(stg + OSM_BH + off, g_wrmt_hi + gb);
                cpa16(stg + OSM_BL + off, g_wrmt_lo + gb);
            }
        }
        cpa_commit();
    };

    load_tiles(0, 0);
    for (int ch = 0; ch < 3; ++ch) {
        if (ch + 1 < 3) { load_tiles((ch + 1) & 1, ch + 1); cpa_wait<1>(); }
        else            { cpa_wait<0>(); }
        __syncthreads();

        const uint32_t stg = sb + (ch & 1) * OST;
#pragma unroll
        for (int ks = 0; ks < 4; ++ks) {
            const uint32_t kof = (uint32_t)(ks * 32);
            uint32_t ah[4][4], al[4][4];
#pragma unroll
            for (int mt = 0; mt < 4; ++mt) {
                const uint32_t ao = a_base + (uint32_t)(mt * 16 * 128) + kof;
                ldsm4(ah[mt][0], ah[mt][1], ah[mt][2], ah[mt][3], stg + OSM_AH + sw128(ao));
                ldsm4(al[mt][0], al[mt][1], al[mt][2], al[mt][3], stg + OSM_AL + sw128(ao));
            }
#pragma unroll
            for (int p = 0; p < 4; ++p) {
                uint32_t bh[4], bl[4];
                const uint32_t boff = (uint32_t)((b_row + p * 16) * 128) + b_coff + kof;
                ldsm4(bh[0], bh[1], bh[2], bh[3], stg + OSM_BH + sw128(boff));
                ldsm4(bl[0], bl[1], bl[2], bl[3], stg + OSM_BL + sw128(boff));
#pragma unroll
                for (int mt = 0; mt < 4; ++mt) {
                    mma16816(c[mt][2 * p],     ah[mt], bh);
                    mma16816(c[mt][2 * p + 1], ah[mt], bh + 2);
                    mma16816(c[mt][2 * p],     ah[mt], bl);
                    mma16816(c[mt][2 * p + 1], ah[mt], bl + 2);
                    mma16816(c[mt][2 * p],     al[mt], bh);
                    mma16816(c[mt][2 * p + 1], al[mt], bh + 2);
                }
            }
        }
        __syncthreads();
    }

#pragma unroll
    for (int mt = 0; mt < 4; ++mt) {
#pragma unroll
        for (int nt = 0; nt < 8; ++nt) {
#pragma unroll
            for (int j = 0; j < 4; ++j) {
                const int r   = m0 + wm * 64 + mt * 16 + (lane >> 2) + (j >= 2 ? 8 : 0);
                const int col = n0 + wn * 64 + nt * 8 + (lane & 3) * 2 + (j & 1);
                const float v = c[mt][nt][j] + g_brm[col];
                const int token = r >> 4;
                const int slot  = r & 15;
                const size_t base = (slot < NSn) ? 0 : (size_t)BS_TOK * NSn * MEMn;
                C[base + (size_t)(token * NSn + (slot & 7)) * MEMn + col] = v;
            }
        }
    }
}

// ---------------------------------------------------------------------------
// Host launcher. Launch order: prep(0), gemm_q(1), attn_part(2),
// merge_gather(3 <- profiled), gemm_out(4).
// ---------------------------------------------------------------------------
extern "C" void kernel_launch(void* const* d_in, const int* in_sizes, int n_in,
                              void* d_out, int out_size)
{
    const float* x      = (const float*)d_in[0];
    const float* Wq     = (const float*)d_in[1];
    const float* bq     = (const float*)d_in[2];
    const float* ln_g   = (const float*)d_in[3];
    const float* ln_b   = (const float*)d_in[4];
    const float* keys   = (const float*)d_in[5];
    const float* values = (const float*)d_in[6];
    const float* Wres   = (const float*)d_in[7];
    const float* bres   = (const float*)d_in[8];
    const float* Wmem   = (const float*)d_in[9];
    const float* bmem   = (const float*)d_in[10];
    float* out = (float*)d_out;

    cudaFuncSetAttribute(gemm_q_kernel,    cudaFuncAttributeMaxDynamicSharedMemorySize, GEMMQ_SMEM);
    cudaFuncSetAttribute(gemm_out_kernel,  cudaFuncAttributeMaxDynamicSharedMemorySize, GEMMO_SMEM);
    cudaFuncSetAttribute(attn_part_kernel, cudaFuncAttributeMaxDynamicSharedMemorySize, ATTN_SMEM);

    prep_all<<<7042, 256>>>(x, Wq, keys, Wres, Wmem, bres, bmem);
    gemm_q_kernel<<<dim3(8, 16), 256, GEMMQ_SMEM>>>(bq, ln_g, ln_b);
    attn_part_kernel<<<dim3(32, 16, 4), 256, ATTN_SMEM>>>();
    attn_merge_gather<<<512, 256>>>(values);        // profiled (launch idx 3)
    gemm_out_kernel<<<dim3(2, 256), 256, GEMMO_SMEM>>>(out);
}

// round 17
// speedup vs baseline: 1.2265x; 1.0839x over previous
#include <cuda_runtime.h>
#include <cuda_bf16.h>
#include <math.h>
#include <float.h>
#include <stdint.h>

#define BS_TOK 2048
#define NQn 16
#define NSn 8
#define KDn 64
#define NKn 2048
#define VDn 128
#define MEMn 512
#define LN_EPS 1e-5f
#define NROWS (BS_TOK * NQn)

// ---------------------------------------------------------------------------
// Scratch globals
// ---------------------------------------------------------------------------
__device__ __nv_bfloat16 g_xhi[BS_TOK * 512],        g_xlo[BS_TOK * 512];
__device__ __nv_bfloat16 g_wqt_hi[1024 * 512],       g_wqt_lo[1024 * 512];
__device__ __nv_bfloat16 g_qhi[NROWS * KDn],         g_qlo[NROWS * KDn];
__device__ __nv_bfloat16 g_khi[NSn * NKn * KDn],     g_klo[NSn * NKn * KDn];
__device__ __nv_bfloat16 g_wmemt_hi[MEMn * VDn],     g_wmemt_lo[MEMn * VDn];
__device__ __nv_bfloat16 g_wrmt_hi[MEMn * KDn],      g_wrmt_lo[MEMn * KDn];
__device__ float         g_brm[MEMn];
__device__ __nv_bfloat16 g_atthi[NROWS * VDn],       g_attlo[NROWS * VDn];
__device__ int g_topp[(size_t)NROWS * 128];

// ---------------------------------------------------------------------------
// Helpers
// ---------------------------------------------------------------------------
__device__ __forceinline__ uint32_t smem_u32(const void* p) {
    uint32_t a;
    asm("{ .reg .u64 t; cvta.to.shared.u64 t, %1; cvt.u32.u64 %0, t; }" : "=r"(a) : "l"(p));
    return a;
}
__device__ __forceinline__ uint32_t sw128(uint32_t off) { return off ^ ((off >> 3) & 0x70); }

__device__ __forceinline__ void mma16816(float c[4], const uint32_t a[4], const uint32_t b[2])
{
    asm("mma.sync.aligned.m16n8k16.row.col.f32.bf16.bf16.f32 "
        "{%0,%1,%2,%3},{%4,%5,%6,%7},{%8,%9},{%0,%1,%2,%3};"
        : "+f"(c[0]), "+f"(c[1]), "+f"(c[2]), "+f"(c[3])
        : "r"(a[0]), "r"(a[1]), "r"(a[2]), "r"(a[3]), "r"(b[0]), "r"(b[1]));
}
__device__ __forceinline__ void ldsm4(uint32_t& r0, uint32_t& r1, uint32_t& r2, uint32_t& r3, uint32_t addr)
{
    asm volatile("ldmatrix.sync.aligned.m8n8.x4.shared.b16 {%0,%1,%2,%3}, [%4];"
                 : "=r"(r0), "=r"(r1), "=r"(r2), "=r"(r3) : "r"(addr));
}
__device__ __forceinline__ void cpa16(uint32_t s, const void* g) {
    asm volatile("cp.async.cg.shared.global [%0], [%1], 16;" :: "r"(s), "l"(g));
}
__device__ __forceinline__ void cpa_commit() { asm volatile("cp.async.commit_group;" ::: "memory"); }
template<int N> __device__ __forceinline__ void cpa_wait() {
    asm volatile("cp.async.wait_group %0;" :: "n"(N) : "memory");
}
__device__ __forceinline__ void split_bf16(float v, __nv_bfloat16& h, __nv_bfloat16& l) {
    h = __float2bfloat16(v);
    l = __float2bfloat16(v - __bfloat162float(h));
}
__device__ __forceinline__ int packsc(float s, int idx) {
    const int q = __float2int_rn(s * 32768.f);
    return (q << 11) | (2047 - idx);
}
__device__ __forceinline__ void insp(int s, int tv[8]) {
#pragma unroll
    for (int i = 0; i < 8; ++i) {
        const int lo = min(tv[i], s);
        tv[i] = max(tv[i], s);
        s = lo;
    }
}

// ---------------------------------------------------------------------------
// Unified prep (R16 proven): x | Wmem/Wrm/brm | Wq transpose | key norm
// ---------------------------------------------------------------------------
__global__ void prep_all(const float* __restrict__ x,
                         const float* __restrict__ Wq,
                         const float* __restrict__ keys,
                         const float* __restrict__ Wres, const float* __restrict__ Wmem,
                         const float* __restrict__ bres, const float* __restrict__ bmem)
{
    __shared__ float tile[32][33];
    const int b = blockIdx.x;
    const int tid = threadIdx.x;
    __nv_bfloat16 h, l;
    if (b < 4096) {
        const int i = b * 256 + tid;
        split_bf16(x[i], h, l);
        g_xhi[i] = h; g_xlo[i] = l;
    } else if (b < 4352) {
        const int i = (b - 4096) * 256 + tid;
        const int k = i >> 9, n = i & 511;
        split_bf16(Wmem[i], h, l);
        g_wmemt_hi[(size_t)n * 128 + k] = h;
        g_wmemt_lo[(size_t)n * 128 + k] = l;
    } else if (b < 4480) {
        const int i = (b - 4352) * 256 + tid;
        const int m = i >> 9, n = i & 511;
        float acc = 0.f;
#pragma unroll 8
        for (int k = 0; k < VDn; ++k)
            acc += Wres[m * VDn + k] * Wmem[k * MEMn + n];
        split_bf16(acc, h, l);
        g_wrmt_hi[(size_t)n * KDn + m] = h;
        g_wrmt_lo[(size_t)n * KDn + m] = l;
    } else if (b < 4482) {
        const int n = (b - 4480) * 256 + tid;
        float acc = bmem[n];
#pragma unroll 8
        for (int k = 0; k < VDn; ++k)
            acc += bres[k] * Wmem[k * MEMn + n];
        g_brm[n] = acc;
    } else if (b < 4994) {
        const int t  = b - 4482;
        const int n0 = (t & 31) << 5;
        const int k0 = (t >> 5) << 5;
        const int tx = tid & 31;
        const int ty = tid >> 5;
#pragma unroll
        for (int i = 0; i < 4; ++i)
            tile[ty + 8 * i][tx] = Wq[(size_t)(k0 + ty + 8 * i) * 1024 + n0 + tx];
        __syncthreads();
#pragma unroll
        for (int i = 0; i < 4; ++i) {
            split_bf16(tile[tx][ty + 8 * i], h, l);
            const size_t o = (size_t)(n0 + ty + 8 * i) * 512 + k0 + tx;
            g_wqt_hi[o] = h; g_wqt_lo[o] = l;
        }
    } else {
        const int warp = (b - 4994) * 8 + (tid >> 5);
        const int lane = tid & 31;
        const float* src = keys + (size_t)warp * KDn;
        float v0 = src[lane], v1 = src[lane + 32];
        float sq = v0 * v0 + v1 * v1;
#pragma unroll
        for (int o = 16; o > 0; o >>= 1) sq += __shfl_xor_sync(0xffffffffu, sq, o);
        const float scale = rsqrtf(sq);
        split_bf16(v0 * scale, h, l); g_khi[(size_t)warp * KDn + lane] = h;      g_klo[(size_t)warp * KDn + lane] = l;
        split_bf16(v1 * scale, h, l); g_khi[(size_t)warp * KDn + lane + 32] = h; g_klo[(size_t)warp * KDn + lane + 32] = l;
    }
}

// ---------------------------------------------------------------------------
// gemm_q: double-buffered, LN epilogue (R14 proven config).
// ---------------------------------------------------------------------------
#define GST 65536
#define GSM_AH 0
#define GSM_AL 16384
#define GSM_BH 32768
#define GSM_BL 49152
#define GEMMQ_SMEM (2 * GST)

__global__ __launch_bounds__(256) void gemm_q_kernel(const float* __restrict__ bias,
                                                     const float* __restrict__ gamma,
                                                     const float* __restrict__ beta)
{
    extern __shared__ char smem[];
    const uint32_t sb = smem_u32(smem);
    const int tid  = threadIdx.x;
    const int lane = tid & 31;
    const int w    = tid >> 5;
    const int wm   = w & 3;
    const int wn   = w >> 2;
    const int m0   = blockIdx.y << 7;
    const int n0   = blockIdx.x << 7;
    const int K    = 512;

    float c[2][8][4];
#pragma unroll
    for (int mt = 0; mt < 2; ++mt)
#pragma unroll
        for (int nt = 0; nt < 8; ++nt)
#pragma unroll
            for (int j = 0; j < 4; ++j) c[mt][nt][j] = 0.f;

    const uint32_t a_off0 = (uint32_t)((wm * 32 + (lane & 15)) * 128 + ((lane >> 4) << 4));
    const uint32_t a_off1 = (uint32_t)((wm * 32 + 16 + (lane & 15)) * 128 + ((lane >> 4) << 4));
    const uint32_t b_row  = (uint32_t)(wn * 64 + (lane & 7) + ((lane >> 4) << 3));
    const uint32_t b_coff = (uint32_t)(((lane >> 3) & 1) << 4);

    auto load_tiles = [&](int stage, int ch) {
        const int k0 = ch << 6;
        const uint32_t stg = sb + stage * GST;
#pragma unroll
        for (int it = tid; it < 1024; it += 256) {
            const int r = it >> 3, p = it & 7;
            const uint32_t off = sw128((uint32_t)(r * 128 + p * 16));
            const size_t ga = (size_t)(m0 + r) * K + k0 + p * 8;
            cpa16(stg + GSM_AH + off, g_xhi + ga);
            cpa16(stg + GSM_AL + off, g_xlo + ga);
            const size_t gb = (size_t)(n0 + r) * K + k0 + p * 8;
            cpa16(stg + GSM_BH + off, g_wqt_hi + gb);
            cpa16(stg + GSM_BL + off, g_wqt_lo + gb);
        }
        cpa_commit();
    };

    load_tiles(0, 0);
    for (int ch = 0; ch < 8; ++ch) {
        if (ch + 1 < 8) { load_tiles((ch + 1) & 1, ch + 1); cpa_wait<1>(); }
        else            { cpa_wait<0>(); }
        __syncthreads();

        const uint32_t stg = sb + (ch & 1) * GST;
#pragma unroll
        for (int ks = 0; ks < 4; ++ks) {
            const uint32_t kof = (uint32_t)(ks * 32);
            uint32_t ah0[4], ah1[4], al0[4], al1[4];
            ldsm4(ah0[0], ah0[1], ah0[2], ah0[3], stg + GSM_AH + sw128(a_off0 + kof));
            ldsm4(ah1[0], ah1[1], ah1[2], ah1[3], stg + GSM_AH + sw128(a_off1 + kof));
            ldsm4(al0[0], al0[1], al0[2], al0[3], stg + GSM_AL + sw128(a_off0 + kof));
            ldsm4(al1[0], al1[1], al1[2], al1[3], stg + GSM_AL + sw128(a_off1 + kof));
#pragma unroll
            for (int p = 0; p < 4; ++p) {
                uint32_t bh[4], bl[4];
                const uint32_t boff = (uint32_t)((b_row + p * 16) * 128) + b_coff + kof;
                ldsm4(bh[0], bh[1], bh[2], bh[3], stg + GSM_BH + sw128(boff));
                ldsm4(bl[0], bl[1], bl[2], bl[3], stg + GSM_BL + sw128(boff));
                mma16816(c[0][2 * p],     ah0, bh);      mma16816(c[1][2 * p],     ah1, bh);
                mma16816(c[0][2 * p + 1], ah0, bh + 2);  mma16816(c[1][2 * p + 1], ah1, bh + 2);
                mma16816(c[0][2 * p],     ah0, bl);      mma16816(c[1][2 * p],     ah1, bl);
                mma16816(c[0][2 * p + 1], ah0, bl + 2);  mma16816(c[1][2 * p + 1], ah1, bl + 2);
                mma16816(c[0][2 * p],     al0, bh);      mma16816(c[1][2 * p],     al1, bh);
                mma16816(c[0][2 * p + 1], al0, bh + 2);  mma16816(c[1][2 * p + 1], al1, bh + 2);
            }
        }
        __syncthreads();
    }

#pragma unroll
    for (int mt = 0; mt < 2; ++mt) {
#pragma unroll
        for (int rh = 0; rh < 2; ++rh) {
            const int r = m0 + wm * 32 + mt * 16 + (lane >> 2) + rh * 8;
            float vals[16];
            float s = 0.f, s2 = 0.f;
#pragma unroll
            for (int nt = 0; nt < 8; ++nt)
#pragma unroll
                for (int jj = 0; jj < 2; ++jj) {
                    const int col = n0 + wn * 64 + nt * 8 + (lane & 3) * 2 + jj;
                    float v = c[mt][nt][rh * 2 + jj] + __ldg(bias + col);
                    vals[nt * 2 + jj] = v;
                    s += v; s2 += v * v;
                }
            s  += __shfl_xor_sync(0xffffffffu, s, 1);
            s  += __shfl_xor_sync(0xffffffffu, s, 2);
            s2 += __shfl_xor_sync(0xffffffffu, s2, 1);
            s2 += __shfl_xor_sync(0xffffffffu, s2, 2);
            const float mu  = s * (1.f / 64.f);
            const float var = s2 * (1.f / 64.f) - mu * mu;
            const float inv = rsqrtf(var + LN_EPS);
            const int slot = (n0 + wn * 64) >> 6;
#pragma unroll
            for (int nt = 0; nt < 8; ++nt) {
                const int kd = nt * 8 + (lane & 3) * 2;
                __nv_bfloat16 h0, l0, h1, l1;
                float o0 = (vals[nt * 2]     - mu) * inv * __ldg(gamma + kd)     + __ldg(beta + kd);
                float o1 = (vals[nt * 2 + 1] - mu) * inv * __ldg(gamma + kd + 1) + __ldg(beta + kd + 1);
                split_bf16(o0, h0, l0); split_bf16(o1, h1, l1);
                const size_t qi = ((size_t)r * NQn + slot) * KDn + kd;
                __nv_bfloat162 ph; ph.x = h0; ph.y = h1;
                __nv_bfloat162 pl; pl.x = l0; pl.y = l1;
                *(__nv_bfloat162*)(g_qhi + qi) = ph;
                *(__nv_bfloat162*)(g_qlo + qi) = pl;
            }
        }
    }
}

// ---------------------------------------------------------------------------
// attn_part (R12/R14 proven config)
// ---------------------------------------------------------------------------
#define ASM_QH 0
#define ASM_QL 8192
#define ASM_KH 16384
#define ASM_KL 24576
#define ASM_SC 32768
#define SC_PITCH 68
#define ATTN_SMEM (32768 + 64 * SC_PITCH * 4)

__global__ __launch_bounds__(256, 3) void attn_part_kernel()
{
    extern __shared__ char smem[];
    float* sc = (float*)(smem + ASM_SC);
    const uint32_t sb = smem_u32(smem);
    const int tid  = threadIdx.x;
    const int lane = tid & 31;
    const int w    = tid >> 5;
    const int wm   = w & 3;
    const int wn   = w >> 2;
    const int slot = blockIdx.y;
    const int t0   = blockIdx.x << 6;
    const int part = blockIdx.z;
    const int kbase = part << 9;

#pragma unroll
    for (int it = tid; it < 512; it += 256) {
        const int r = it >> 3, p = it & 7;
        const uint32_t off = sw128((uint32_t)(r * 128 + p * 16));
        const size_t g = ((size_t)(t0 + r) * NQn + slot) * KDn + p * 8;
        *(uint4*)(smem + ASM_QH + off) = *(const uint4*)(g_qhi + g);
        *(uint4*)(smem + ASM_QL + off) = *(const uint4*)(g_qlo + g);
    }

    const __nv_bfloat16* kbh = g_khi + ((size_t)(slot & 7) * NKn + kbase) * KDn;
    const __nv_bfloat16* kbl = g_klo + ((size_t)(slot & 7) * NKn + kbase) * KDn;

    const uint32_t a_off = (uint32_t)((wm * 16 + (lane & 15)) * 128 + ((lane >> 4) << 4));
    const uint32_t b_row = (uint32_t)(wn * 32 + (lane & 7) + ((lane >> 4) << 3));
    const uint32_t b_coff = (uint32_t)(((lane >> 3) & 1) << 4);

    int tv[8];
#pragma unroll
    for (int i = 0; i < 8; ++i) tv[i] = (int)0x80000000;

    for (int ch = 0; ch < 8; ++ch) {
#pragma unroll
        for (int it = tid; it < 512; it += 256) {
            const int r = it >> 3, p = it & 7;
            const uint32_t off = sw128((uint32_t)(r * 128 + p * 16));
            const size_t g = (size_t)(ch * 64 + r) * KDn + p * 8;
            *(uint4*)(smem + ASM_KH + off) = *(const uint4*)(kbh + g);
            *(uint4*)(smem + ASM_KL + off) = *(const uint4*)(kbl + g);
        }
        __syncthreads();

        float c[4][4];
#pragma unroll
        for (int nt = 0; nt < 4; ++nt)
#pragma unroll
            for (int j = 0; j < 4; ++j) c[nt][j] = 0.f;

#pragma unroll
        for (int ks = 0; ks < 4; ++ks) {
            const uint32_t kof = (uint32_t)(ks * 32);
            uint32_t ah[4], al[4];
            ldsm4(ah[0], ah[1], ah[2], ah[3], sb + ASM_QH + sw128(a_off + kof));
            ldsm4(al[0], al[1], al[2], al[3], sb + ASM_QL + sw128(a_off + kof));
#pragma unroll
            for (int p = 0; p < 2; ++p) {
                uint32_t bh[4], bl[4];
                const uint32_t boff = (uint32_t)((b_row + p * 16) * 128) + b_coff + kof;
                ldsm4(bh[0], bh[1], bh[2], bh[3], sb + ASM_KH + sw128(boff));
                ldsm4(bl[0], bl[1], bl[2], bl[3], sb + ASM_KL + sw128(boff));
                mma16816(c[2 * p],     ah, bh);
                mma16816(c[2 * p + 1], ah, bh + 2);
                mma16816(c[2 * p],     ah, bl);
                mma16816(c[2 * p + 1], ah, bl + 2);
                mma16816(c[2 * p],     al, bh);
                mma16816(c[2 * p + 1], al, bh + 2);
            }
        }

        {
            const int r = wm * 16 + (lane >> 2);
#pragma unroll
            for (int nt = 0; nt < 4; ++nt) {
                const int cb = wn * 32 + nt * 8 + (lane & 3) * 2;
                sc[r * SC_PITCH + cb]           = c[nt][0];
                sc[r * SC_PITCH + cb + 1]       = c[nt][1];
                sc[(r + 8) * SC_PITCH + cb]     = c[nt][2];
                sc[(r + 8) * SC_PITCH + cb + 1] = c[nt][3];
            }
        }
        __syncthreads();

        {
            const int t = tid >> 2, base = (tid & 3) * 16;
            const float4* rowp = (const float4*)(sc + t * SC_PITCH + base);
#pragma unroll
            for (int j4 = 0; j4 < 4; ++j4) {
                const float4 v = rowp[j4];
                const float m4 = fmaxf(fmaxf(v.x, v.y), fmaxf(v.z, v.w));
                if (packsc(m4, 0) > tv[7]) {
                    const int gi = kbase + ch * 64 + base + j4 * 4;
                    insp(packsc(v.x, gi),     tv);
                    insp(packsc(v.y, gi + 1), tv);
                    insp(packsc(v.z, gi + 2), tv);
                    insp(packsc(v.w, gi + 3), tv);
                }
            }
        }
    }

    {
        const int t = tid >> 2, sub = tid & 3;
        const size_t row = (size_t)(t0 + t) * NQn + slot;
        int* dv = g_topp + row * 128 + part * 32 + sub * 8;
#pragma unroll
        for (int i = 0; i < 8; ++i) dv[i] = tv[i];
    }
}

// ---------------------------------------------------------------------------
// Fused merge + softmax + V-gather. 8 threads/row (16 dims each), 32 rows/block,
// grid 1024 -> ~2x occupancy vs R16 for the latency-bound gather.
// ---------------------------------------------------------------------------
__global__ __launch_bounds__(256) void attn_merge_gather(const float* __restrict__ values)
{
    __shared__ int   stg[32][33];
    __shared__ float spw[32][8];
    __shared__ int   spi[32][8];
    const int g = blockIdx.x * 256 + threadIdx.x;
    const int row = g >> 3;
    const int oct = g & 7;
    const int lrow = threadIdx.x >> 3;
    if (row >= NROWS) return;

    // Stage 1: octs 0-3 each merge 4 sorted runs of 8 -> top-8
    if (oct < 4) {
        const int4* src = (const int4*)(g_topp + (size_t)row * 128 + oct * 32);
        int rn[4][8];
#pragma unroll
        for (int rr = 0; rr < 4; ++rr) {
            const int4 a = src[rr * 2];
            const int4 b = src[rr * 2 + 1];
            rn[rr][0] = a.x; rn[rr][1] = a.y; rn[rr][2] = a.z; rn[rr][3] = a.w;
            rn[rr][4] = b.x; rn[rr][5] = b.y; rn[rr][6] = b.z; rn[rr][7] = b.w;
        }
        int ptr[4] = {0, 0, 0, 0};
        int out[8];
#pragma unroll
        for (int s = 0; s < 8; ++s) {
            int best = (int)0x80000000, br = 0;
#pragma unroll
            for (int run = 0; run < 4; ++run) {
                const int cv = (ptr[run] < 8) ? rn[run][ptr[run] & 7] : (int)0x80000000;
                if (cv > best) { best = cv; br = run; }
            }
            out[s] = best; ptr[br]++;
        }
#pragma unroll
        for (int i = 0; i < 8; ++i) stg[lrow][oct * 8 + i] = out[i];
    }
    __syncthreads();

    // Stage 2: oct 0 finalizes + softmax
    if (oct == 0) {
        int ptr[4] = {0, 0, 0, 0};
        int fin[8];
#pragma unroll
        for (int s = 0; s < 8; ++s) {
            int best = (int)0x80000000, br = 0;
#pragma unroll
            for (int run = 0; run < 4; ++run) {
                const int cv = (ptr[run] < 8) ? stg[lrow][run * 8 + ptr[run]] : (int)0x80000000;
                if (cv > best) { best = cv; br = run; }
            }
            fin[s] = best; ptr[br]++;
        }
        float sv[8];
#pragma unroll
        for (int i = 0; i < 8; ++i) {
            spi[lrow][i] = 2047 - (fin[i] & 2047);
            sv[i] = (float)(fin[i] >> 11) * (1.f / 32768.f);
        }
        const float mx = sv[0];
        float pr[8], denom = 0.f;
#pragma unroll
        for (int i = 0; i < 8; ++i) { pr[i] = expf(sv[i] - mx); denom += pr[i]; }
        const float inv = 1.f / denom;
#pragma unroll
        for (int i = 0; i < 8; ++i) spw[lrow][i] = pr[i] * inv;
    }
    __syncthreads();

    // Gather: 8 threads/row x 16 dims (8 keys x 4 float4 loads per thread)
    {
        const int d0 = oct * 16;
        const int slot = row & 15;
        float pr[8]; int ir[8];
#pragma unroll
        for (int i = 0; i < 8; ++i) { pr[i] = spw[lrow][i]; ir[i] = spi[lrow][i]; }
        const float* vb = values + (size_t)(slot & 7) * NKn * VDn + d0;
        __nv_bfloat16* oh = g_atthi + (size_t)row * VDn + d0;
        __nv_bfloat16* ol = g_attlo + (size_t)row * VDn + d0;
#pragma unroll
        for (int dd = 0; dd < 16; dd += 4) {
            float4 acc = make_float4(0.f, 0.f, 0.f, 0.f);
#pragma unroll
            for (int i = 0; i < 8; ++i) {
                const float4 vv = *(const float4*)(vb + (size_t)ir[i] * VDn + dd);
                acc.x += pr[i] * vv.x; acc.y += pr[i] * vv.y;
                acc.z += pr[i] * vv.z; acc.w += pr[i] * vv.w;
            }
            __nv_bfloat16 h, l;
            split_bf16(acc.x, h, l); oh[dd]     = h; ol[dd]     = l;
            split_bf16(acc.y, h, l); oh[dd + 1] = h; ol[dd + 1] = l;
            split_bf16(acc.z, h, l); oh[dd + 2] = h; ol[dd + 2] = l;
            split_bf16(acc.w, h, l); oh[dd + 3] = h; ol[dd + 3] = l;
        }
    }
}

// ---------------------------------------------------------------------------
// gemm_out: 128x256 tiles, double-buffered (R15 proven config).
// ---------------------------------------------------------------------------
#define OST 98304
#define OSM_AH 0
#define OSM_AL 16384
#define OSM_BH 32768
#define OSM_BL 65536
#define GEMMO_SMEM (2 * OST)

__global__ __launch_bounds__(256) void gemm_out_kernel(float* __restrict__ C)
{
    extern __shared__ char smem[];
    const uint32_t sb = smem_u32(smem);
    const int tid  = threadIdx.x;
    const int lane = tid & 31;
    const int w    = tid >> 5;
    const int wm   = w & 1;
    const int wn   = w >> 1;
    const int m0   = blockIdx.y << 7;
    const int n0   = blockIdx.x << 8;

    float c[4][8][4];
#pragma unroll
    for (int mt = 0; mt < 4; ++mt)
#pragma unroll
        for (int nt = 0; nt < 8; ++nt)
#pragma unroll
            for (int j = 0; j < 4; ++j) c[mt][nt][j] = 0.f;

    const uint32_t a_base = (uint32_t)((wm * 64 + (lane & 15)) * 128 + ((lane >> 4) << 4));
    const uint32_t b_row  = (uint32_t)(wn * 64 + (lane & 7) + ((lane >> 4) << 3));
    const uint32_t b_coff = (uint32_t)(((lane >> 3) & 1) << 4);

    auto load_tiles = [&](int stage, int ch) {
        const uint32_t stg = sb + stage * OST;
#pragma unroll
        for (int it = tid; it < 1024; it += 256) {
            const int r = it >> 3, p = it & 7;
            const uint32_t off = sw128((uint32_t)(r * 128 + p * 16));
            if (ch < 2) {
                const size_t ga = (size_t)(m0 + r) * VDn + (ch << 6) + p * 8;
                cpa16(stg + OSM_AH + off, g_atthi + ga);
                cpa16(stg + OSM_AL + off, g_attlo + ga);
            } else {
                const size_t ga = (size_t)(m0 + r) * KDn + p * 8;
                cpa16(stg + OSM_AH + off, g_qhi + ga);
                cpa16(stg + OSM_AL + off, g_qlo + ga);
            }
        }
#pragma unroll
        for (int it = tid; it < 2048; it += 256) {
            const int r = it >> 3, p = it & 7;
            const uint32_t off = sw128((uint32_t)(r * 128 + p * 16));
            if (ch < 2) {
                const size_t gb = (size_t)(n0 + r) * VDn + (ch << 6) + p * 8;
                cpa16(stg + OSM_BH + off, g_wmemt_hi + gb);
                cpa16(stg + OSM_BL + off, g_wmemt_lo + gb);
            } else {
                const size_t gb = (size_t)(n0 + r) * KDn + p * 8;
                cpa16(stg + OSM_BH + off, g_wrmt_hi + gb);
                cpa16(stg + OSM_BL + off, g_wrmt_lo + gb);
            }
        }
        cpa_commit();
    };

    load_tiles(0, 0);
    for (int ch = 0; ch < 3; ++ch) {
        if (ch + 1 < 3) { load_tiles((ch + 1) & 1, ch + 1); cpa_wait<1>(); }
        else            { cpa_wait<0>(); }
        __syncthreads();

        const uint32_t stg = sb + (ch & 1) * OST;
#pragma unroll
        for (int ks = 0; ks < 4; ++ks) {
            const uint32_t kof = (uint32_t)(ks * 32);
            uint32_t ah[4][4], al[4][4];
#pragma unroll
            for (int mt = 0; mt < 4; ++mt) {
                const uint32_t ao = a_base + (uint32_t)(mt * 16 * 128) + kof;
                ldsm4(ah[mt][0], ah[mt][1], ah[mt][2], ah[mt][3], stg + OSM_AH + sw128(ao));
                ldsm4(al[mt][0], al[mt][1], al[mt][2], al[mt][3], stg + OSM_AL + sw128(ao));
            }
#pragma unroll
            for (int p = 0; p < 4; ++p) {
                uint32_t bh[4], bl[4];
                const uint32_t boff = (uint32_t)((b_row + p * 16) * 128) + b_coff + kof;
                ldsm4(bh[0], bh[1], bh[2], bh[3], stg + OSM_BH + sw128(boff));
                ldsm4(bl[0], bl[1], bl[2], bl[3], stg + OSM_BL + sw128(boff));
#pragma unroll
                for (int mt = 0; mt < 4; ++mt) {
                    mma16816(c[mt][2 * p],     ah[mt], bh);
                    mma16816(c[mt][2 * p + 1], ah[mt], bh + 2);
                    mma16816(c[mt][2 * p],     ah[mt], bl);
                    mma16816(c[mt][2 * p + 1], ah[mt], bl + 2);
                    mma16816(c[mt][2 * p],     al[mt], bh);
                    mma16816(c[mt][2 * p + 1], al[mt], bh + 2);
                }
            }
        }
        __syncthreads();
    }

#pragma unroll
    for (int mt = 0; mt < 4; ++mt) {
#pragma unroll
        for (int nt = 0; nt < 8; ++nt) {
#pragma unroll
            for (int j = 0; j < 4; ++j) {
                const int r   = m0 + wm * 64 + mt * 16 + (lane >> 2) + (j >= 2 ? 8 : 0);
                const int col = n0 + wn * 64 + nt * 8 + (lane & 3) * 2 + (j & 1);
                const float v = c[mt][nt][j] + g_brm[col];
                const int token = r >> 4;
                const int slot  = r & 15;
                const size_t base = (slot < NSn) ? 0 : (size_t)BS_TOK * NSn * MEMn;
                C[base + (size_t)(token * NSn + (slot & 7)) * MEMn + col] = v;
            }
        }
    }
}

// ---------------------------------------------------------------------------
// Host launcher. merge_gather stays at launch idx 3 (profiled).
// ---------------------------------------------------------------------------
extern "C" void kernel_launch(void* const* d_in, const int* in_sizes, int n_in,
                              void* d_out, int out_size)
{
    const float* x      = (const float*)d_in[0];
    const float* Wq     = (const float*)d_in[1];
    const float* bq     = (const float*)d_in[2];
    const float* ln_g   = (const float*)d_in[3];
    const float* ln_b   = (const float*)d_in[4];
    const float* keys   = (const float*)d_in[5];
    const float* values = (const float*)d_in[6];
    const float* Wres   = (const float*)d_in[7];
    const float* bres   = (const float*)d_in[8];
    const float* Wmem   = (const float*)d_in[9];
    const float* bmem   = (const float*)d_in[10];
    float* out = (float*)d_out;

    cudaFuncSetAttribute(gemm_q_kernel,    cudaFuncAttributeMaxDynamicSharedMemorySize, GEMMQ_SMEM);
    cudaFuncSetAttribute(gemm_out_kernel,  cudaFuncAttributeMaxDynamicSharedMemorySize, GEMMO_SMEM);
    cudaFuncSetAttribute(attn_part_kernel, cudaFuncAttributeMaxDynamicSharedMemorySize, ATTN_SMEM);

    prep_all<<<7042, 256>>>(x, Wq, keys, Wres, Wmem, bres, bmem);
    gemm_q_kernel<<<dim3(8, 16), 256, GEMMQ_SMEM>>>(bq, ln_g, ln_b);
    attn_part_kernel<<<dim3(32, 16, 4), 256, ATTN_SMEM>>>();
    attn_merge_gather<<<1024, 256>>>(values);       // profiled (launch idx 3)
    gemm_out_kernel<<<dim3(2, 256), 256, GEMMO_SMEM>>>(out);
}